// round 5
// baseline (speedup 1.0000x reference)
#include <cuda_runtime.h>
#include <cuda_fp16.h>
#include <math.h>
#include <cstdint>

// Problem constants
#define T_TOK   2048
#define H_DIM   1024
#define E_NUM   16
#define I_DIM   1024
#define NPAIR   (T_TOK*2)
#define WELEM   (E_NUM*I_DIM*H_DIM)   // 16,777,216 per weight tensor

// Scratch (device globals)
__device__ __half g_gate_h[WELEM];        // fp16 weights
__device__ __half g_up_h  [WELEM];
__device__ __half g_down_h[WELEM];
__device__ __half g_xh    [T_TOK * H_DIM];
__device__ __half g_act   [NPAIR * I_DIM];
__device__ float  g_part  [NPAIR * H_DIM];
__device__ int    g_expert_of[NPAIR];
__device__ float  g_weight_of[NPAIR];
__device__ int    g_base [E_NUM];
__device__ int    g_count[E_NUM];
__device__ int    g_pair_token[NPAIR];
__device__ float  g_pair_w   [NPAIR];
__device__ int    g_slot_of  [NPAIR];

// ---------------------------------------------------------------------------
// helpers
// ---------------------------------------------------------------------------
__device__ __forceinline__ uint32_t smem_u32(const void* p) {
    uint32_t a;
    asm("{ .reg .u64 t; cvta.to.shared.u64 t, %1; cvt.u32.u64 %0, t; }" : "=r"(a) : "l"(p));
    return a;
}
__device__ __forceinline__ void ldsm_x4(uint32_t* r, uint32_t addr) {
    asm volatile("ldmatrix.sync.aligned.m8n8.x4.shared.b16 {%0,%1,%2,%3}, [%4];"
                 : "=r"(r[0]), "=r"(r[1]), "=r"(r[2]), "=r"(r[3]) : "r"(addr));
}
__device__ __forceinline__ void mma16816(float* c, const uint32_t* a, const uint32_t* b) {
    asm volatile("mma.sync.aligned.m16n8k16.row.col.f32.f16.f16.f32 "
                 "{%0,%1,%2,%3}, {%4,%5,%6,%7}, {%8,%9}, {%0,%1,%2,%3};"
                 : "+f"(c[0]), "+f"(c[1]), "+f"(c[2]), "+f"(c[3])
                 : "r"(a[0]), "r"(a[1]), "r"(a[2]), "r"(a[3]), "r"(b[0]), "r"(b[1]));
}
__device__ __forceinline__ uint32_t packh2(float x, float y) {
    __half2 h = __floats2half2_rn(x, y);
    return *(uint32_t*)&h;
}
__device__ __forceinline__ void cp16(uint32_t smem_dst, const void* gmem_src) {
    asm volatile("cp.async.cg.shared.global [%0], [%1], 16;"
                 :: "r"(smem_dst), "l"(gmem_src));
}
#define CP_COMMIT() asm volatile("cp.async.commit_group;" ::: "memory")
#define CP_WAIT2()  asm volatile("cp.async.wait_group 2;" ::: "memory")

// smem row pitch: 40 halfs = 80 B (conflict-free ldmatrix, 16B-aligned chunks)
#define PITCH 40
#define ROWB  80
#define STAGES 4

// ---------------------------------------------------------------------------
// 0) fp32 -> fp16 conversion (grid-stride over 8-element packs)
// ---------------------------------------------------------------------------
__global__ void cvt_kernel(const float* __restrict__ src, __half* __restrict__ dst, int n8) {
    int i = blockIdx.x * blockDim.x + threadIdx.x;
    if (i < n8) {
        float4 a = ((const float4*)src)[2*i];
        float4 b = ((const float4*)src)[2*i+1];
        uint4 o;
        o.x = packh2(a.x, a.y); o.y = packh2(a.z, a.w);
        o.z = packh2(b.x, b.y); o.w = packh2(b.z, b.w);
        ((uint4*)dst)[i] = o;
    }
}

// ---------------------------------------------------------------------------
// 1) Router
// ---------------------------------------------------------------------------
__global__ void router_kernel(const float* __restrict__ x,
                              const float* __restrict__ rw) {
    int t = blockIdx.x;
    int warp = threadIdx.x >> 5, lane = threadIdx.x & 31;
    __shared__ float logits[E_NUM];
    const float* xr = x + (size_t)t * H_DIM;
    const float* wr = rw + (size_t)warp * H_DIM;
    float s = 0.f;
    #pragma unroll 4
    for (int h = lane; h < H_DIM; h += 32) s += xr[h] * wr[h];
    #pragma unroll
    for (int o = 16; o; o >>= 1) s += __shfl_xor_sync(0xffffffffu, s, o);
    if (lane == 0) logits[warp] = s;
    __syncthreads();
    if (threadIdx.x == 0) {
        float sc[E_NUM];
        #pragma unroll
        for (int e = 0; e < E_NUM; e++) sc[e] = 1.f / (1.f + expf(-logits[e]));
        int i0 = 0;
        #pragma unroll
        for (int e = 1; e < E_NUM; e++) if (sc[e] > sc[i0]) i0 = e;
        int i1 = -1;
        #pragma unroll
        for (int e = 0; e < E_NUM; e++) {
            if (e == i0) continue;
            if (i1 < 0 || sc[e] > sc[i1]) i1 = e;
        }
        float w0 = sc[i0], w1 = sc[i1];
        float inv = 1.f / (w0 + w1 + 1e-20f);
        g_expert_of[2*t]   = i0;  g_weight_of[2*t]   = w0 * inv;
        g_expert_of[2*t+1] = i1;  g_weight_of[2*t+1] = w1 * inv;
    }
}

// ---------------------------------------------------------------------------
// 2) Build expert-sorted pair lists
// ---------------------------------------------------------------------------
__global__ void build_kernel() {
    __shared__ unsigned char eid[NPAIR];
    __shared__ int cnt[E_NUM], bs[E_NUM];
    int tid = threadIdx.x;
    for (int p = tid; p < NPAIR; p += blockDim.x)
        eid[p] = (unsigned char)g_expert_of[p];
    __syncthreads();
    if (tid < E_NUM) {
        int c = 0;
        for (int p = 0; p < NPAIR; p++) c += (eid[p] == tid);
        cnt[tid] = c;
    }
    __syncthreads();
    if (tid == 0) {
        int acc = 0;
        for (int e = 0; e < E_NUM; e++) { bs[e] = acc; acc += cnt[e]; }
    }
    __syncthreads();
    int w = tid >> 5, lane = tid & 31;
    if (w < E_NUM) {
        int e = w, pos = bs[e];
        for (int p0 = 0; p0 < NPAIR; p0 += 32) {
            int p = p0 + lane;
            bool m = (eid[p] == e);
            unsigned mask = __ballot_sync(0xffffffffu, m);
            if (m) {
                int s = pos + __popc(mask & ((1u << lane) - 1u));
                g_pair_token[s] = p >> 1;
                g_pair_w[s]     = g_weight_of[p];
                g_slot_of[p]    = s;
            }
            pos += __popc(mask);
        }
    }
    if (tid < E_NUM) { g_base[tid] = bs[tid]; g_count[tid] = cnt[tid]; }
}

// ---------------------------------------------------------------------------
// 3) gateup: 4-stage cp.async fp16 pipeline, gate+up fused, SiLU + fold
//    CTA tile 128(M) x 64(N each matrix) x 32(K), 8 warps (4m x 2n) 32x32.
//    dyn smem: A 4x10240 | Bg 4x5120 | Bu 4x5120 = 81920 B
// ---------------------------------------------------------------------------
#define GU_ASTG 10240
#define GU_BSTG 5120
#define GU_OFFA 0
#define GU_OFFG (4*GU_ASTG)
#define GU_OFFU (GU_OFFG + 4*GU_BSTG)
#define GU_SMEM (GU_OFFU + 4*GU_BSTG)

__global__ __launch_bounds__(256)
void gateup_mma(const __half* __restrict__ xh) {
    int e  = blockIdx.z;
    int m0 = blockIdx.y * 128;
    int n0 = blockIdx.x * 64;
    int cnt = g_count[e];
    if (m0 >= cnt) return;
    int bse = g_base[e];

    extern __shared__ char dsm[];
    uint32_t sb = smem_u32(dsm);
    __shared__ int   tok_s[128];
    __shared__ float wrow_s[128];

    int tid = threadIdx.x, lane = tid & 31, wid = tid >> 5;
    if (tid < 128) {
        int m = m0 + tid;
        bool v = m < cnt;
        int mc = v ? m : (cnt - 1);
        tok_s[tid]  = g_pair_token[bse + mc];
        wrow_s[tid] = v ? g_pair_w[bse + m] : 0.f;
    }
    __syncthreads();

    const __half* Gh = g_gate_h + ((size_t)e << 20) + (size_t)n0 * H_DIM;
    const __half* Uh = g_up_h   + ((size_t)e << 20) + (size_t)n0 * H_DIM;

    int wm = wid & 3, wn = wid >> 2;
    int m_base = wm * 32, n_base = wn * 32;

    uint32_t addrA[2];
    #pragma unroll
    for (int i = 0; i < 2; i++)
        addrA[i] = sb + GU_OFFA + (uint32_t)((m_base + i*16 + (lane & 15)) * ROWB) + ((lane >> 4) * 16);
    uint32_t addrBg[2], addrBu[2];
    #pragma unroll
    for (int jj = 0; jj < 2; jj++) {
        uint32_t row = (uint32_t)(n_base + jj*16 + (lane & 7) + (((lane >> 4) & 1) << 3));
        uint32_t off = row * ROWB + (((lane >> 3) & 1) * 16);
        addrBg[jj] = sb + GU_OFFG + off;
        addrBu[jj] = sb + GU_OFFU + off;
    }

    // loader indices
    int ar0 = tid >> 2, ac0 = tid & 3;            // A: 2 chunks/thread
    int br  = tid >> 2, bc  = tid & 3;            // B: 1 chunk/thread each

    float cg[2][4][4] = {}, cu[2][4][4] = {};

    // prologue: stages 0..2
    #pragma unroll
    for (int s = 0; s < STAGES-1; s++) {
        int k0 = s * 32;
        uint32_t dA = sb + GU_OFFA + s * GU_ASTG;
        #pragma unroll
        for (int j = 0; j < 2; j++) {
            int r = ar0 + j*64;
            cp16(dA + r*ROWB + ac0*16, xh + (size_t)tok_s[r] * H_DIM + k0 + ac0*8);
        }
        cp16(sb + GU_OFFG + s*GU_BSTG + br*ROWB + bc*16, Gh + (size_t)br * H_DIM + k0 + bc*8);
        cp16(sb + GU_OFFU + s*GU_BSTG + br*ROWB + bc*16, Uh + (size_t)br * H_DIM + k0 + bc*8);
        CP_COMMIT();
    }

    const int NIT = H_DIM / 32;
    for (int it = 0; it < NIT; it++) {
        CP_WAIT2();
        __syncthreads();
        int cur = it & 3;
        uint32_t offA = (uint32_t)cur * GU_ASTG;
        uint32_t offB = (uint32_t)cur * GU_BSTG;
        #pragma unroll
        for (int ks = 0; ks < 2; ks++) {
            uint32_t a[2][4];
            #pragma unroll
            for (int i = 0; i < 2; i++) ldsm_x4(a[i], addrA[i] + offA + ks*32);
            uint32_t bg[2][4], bu[2][4];
            #pragma unroll
            for (int jj = 0; jj < 2; jj++) {
                ldsm_x4(bg[jj], addrBg[jj] + offB + ks*32);
                ldsm_x4(bu[jj], addrBu[jj] + offB + ks*32);
            }
            #pragma unroll
            for (int i = 0; i < 2; i++)
                #pragma unroll
                for (int jj = 0; jj < 2; jj++) {
                    mma16816(cg[i][2*jj+0], a[i], &bg[jj][0]);
                    mma16816(cg[i][2*jj+1], a[i], &bg[jj][2]);
                    mma16816(cu[i][2*jj+0], a[i], &bu[jj][0]);
                    mma16816(cu[i][2*jj+1], a[i], &bu[jj][2]);
                }
        }
        // issue stage it+3
        if (it + STAGES-1 < NIT) {
            int s = (it + STAGES-1) & 3;
            int k0 = (it + STAGES-1) * 32;
            uint32_t dA = sb + GU_OFFA + s * GU_ASTG;
            #pragma unroll
            for (int j = 0; j < 2; j++) {
                int r = ar0 + j*64;
                cp16(dA + r*ROWB + ac0*16, xh + (size_t)tok_s[r] * H_DIM + k0 + ac0*8);
            }
            cp16(sb + GU_OFFG + s*GU_BSTG + br*ROWB + bc*16, Gh + (size_t)br * H_DIM + k0 + bc*8);
            cp16(sb + GU_OFFU + s*GU_BSTG + br*ROWB + bc*16, Uh + (size_t)br * H_DIM + k0 + bc*8);
        }
        CP_COMMIT();
    }

    // epilogue: act = w * silu(gate) * up -> fp16
    #pragma unroll
    for (int i = 0; i < 2; i++) {
        #pragma unroll
        for (int h = 0; h < 2; h++) {
            int ml = m_base + i*16 + h*8 + (lane >> 2);
            int m  = m0 + ml;
            if (m >= cnt) continue;
            float w = wrow_s[ml];
            __half* arow = g_act + (size_t)(bse + m) * I_DIM + n0;
            #pragma unroll
            for (int j = 0; j < 4; j++) {
                int nl = n_base + j*8 + 2*(lane & 3);
                float g0 = cg[i][j][h*2+0], g1 = cg[i][j][h*2+1];
                float u0 = cu[i][j][h*2+0], u1 = cu[i][j][h*2+1];
                float a0 = w * (g0 / (1.f + __expf(-g0))) * u0;
                float a1 = w * (g1 / (1.f + __expf(-g1))) * u1;
                *(uint32_t*)&arow[nl] = packh2(a0, a1);
            }
        }
    }
}

// ---------------------------------------------------------------------------
// 4) down: 4-stage cp.async fp16 pipeline -> g_part (fp32)
//    CTA tile 128(M) x 128(N) x 32(K), 8 warps (4m x 2n), warp 32x64.
//    dyn smem: A 4x10240 | B 4x10240 = 81920 B
// ---------------------------------------------------------------------------
#define DN_STG  10240
#define DN_OFFA 0
#define DN_OFFB (4*DN_STG)
#define DN_SMEM (8*DN_STG)

__global__ __launch_bounds__(256)
void down_mma() {
    int e  = blockIdx.z;
    int m0 = blockIdx.y * 128;
    int n0 = blockIdx.x * 128;
    int cnt = g_count[e];
    if (m0 >= cnt) return;
    int bse = g_base[e];

    extern __shared__ char dsm[];
    uint32_t sb = smem_u32(dsm);

    int tid = threadIdx.x, lane = tid & 31, wid = tid >> 5;
    int mlim = cnt - m0;

    const __half* Dh = g_down_h + ((size_t)e << 20) + (size_t)n0 * I_DIM;

    int wm = wid & 3, wn = wid >> 2;
    int m_base = wm * 32, n_base = wn * 64;

    uint32_t addrA[2];
    #pragma unroll
    for (int i = 0; i < 2; i++)
        addrA[i] = sb + DN_OFFA + (uint32_t)((m_base + i*16 + (lane & 15)) * ROWB) + ((lane >> 4) * 16);
    uint32_t addrB[4];
    #pragma unroll
    for (int jj = 0; jj < 4; jj++) {
        uint32_t row = (uint32_t)(n_base + jj*16 + (lane & 7) + (((lane >> 4) & 1) << 3));
        addrB[jj] = sb + DN_OFFB + row * ROWB + (((lane >> 3) & 1) * 16);
    }

    int lr = tid >> 2, lc = tid & 3;
    // per-thread clamped A rows
    int ra0 = (lr      < mlim) ? lr      : (mlim - 1);
    int ra1 = (lr + 64 < mlim) ? lr + 64 : (mlim - 1);
    const __half* A0 = g_act + (size_t)(bse + m0 + ra0) * I_DIM;
    const __half* A1 = g_act + (size_t)(bse + m0 + ra1) * I_DIM;

    float cc[2][8][4] = {};

    #pragma unroll
    for (int s = 0; s < STAGES-1; s++) {
        int k0 = s * 32;
        uint32_t dA = sb + DN_OFFA + s * DN_STG;
        uint32_t dB = sb + DN_OFFB + s * DN_STG;
        cp16(dA + lr*ROWB        + lc*16, A0 + k0 + lc*8);
        cp16(dA + (lr+64)*ROWB   + lc*16, A1 + k0 + lc*8);
        cp16(dB + lr*ROWB        + lc*16, Dh + (size_t)lr       * I_DIM + k0 + lc*8);
        cp16(dB + (lr+64)*ROWB   + lc*16, Dh + (size_t)(lr+64)  * I_DIM + k0 + lc*8);
        CP_COMMIT();
    }

    const int NIT = I_DIM / 32;
    for (int it = 0; it < NIT; it++) {
        CP_WAIT2();
        __syncthreads();
        int cur = it & 3;
        uint32_t offA = (uint32_t)cur * DN_STG;
        uint32_t offB = (uint32_t)cur * DN_STG;
        #pragma unroll
        for (int ks = 0; ks < 2; ks++) {
            uint32_t a[2][4];
            #pragma unroll
            for (int i = 0; i < 2; i++) ldsm_x4(a[i], addrA[i] + offA + ks*32);
            uint32_t b[4][4];
            #pragma unroll
            for (int jj = 0; jj < 4; jj++) ldsm_x4(b[jj], addrB[jj] + offB + ks*32);
            #pragma unroll
            for (int i = 0; i < 2; i++)
                #pragma unroll
                for (int jj = 0; jj < 4; jj++) {
                    mma16816(cc[i][2*jj+0], a[i], &b[jj][0]);
                    mma16816(cc[i][2*jj+1], a[i], &b[jj][2]);
                }
        }
        if (it + STAGES-1 < NIT) {
            int s = (it + STAGES-1) & 3;
            int k0 = (it + STAGES-1) * 32;
            uint32_t dA = sb + DN_OFFA + s * DN_STG;
            uint32_t dB = sb + DN_OFFB + s * DN_STG;
            cp16(dA + lr*ROWB      + lc*16, A0 + k0 + lc*8);
            cp16(dA + (lr+64)*ROWB + lc*16, A1 + k0 + lc*8);
            cp16(dB + lr*ROWB      + lc*16, Dh + (size_t)lr      * I_DIM + k0 + lc*8);
            cp16(dB + (lr+64)*ROWB + lc*16, Dh + (size_t)(lr+64) * I_DIM + k0 + lc*8);
        }
        CP_COMMIT();
    }

    #pragma unroll
    for (int i = 0; i < 2; i++) {
        #pragma unroll
        for (int h = 0; h < 2; h++) {
            int ml = m_base + i*16 + h*8 + (lane >> 2);
            int m  = m0 + ml;
            if (m >= cnt) continue;
            float* prow = g_part + (size_t)(bse + m) * H_DIM + n0;
            #pragma unroll
            for (int j = 0; j < 8; j++) {
                int nl = n_base + j*8 + 2*(lane & 3);
                *(float2*)&prow[nl] = make_float2(cc[i][j][h*2+0], cc[i][j][h*2+1]);
            }
        }
    }
}

// ---------------------------------------------------------------------------
// 5) Combine
// ---------------------------------------------------------------------------
__global__ void combine_kernel(float* __restrict__ out) {
    int t = blockIdx.x;
    int s0 = g_slot_of[2*t], s1 = g_slot_of[2*t + 1];
    const float4* p0 = (const float4*)(g_part + (size_t)s0 * H_DIM);
    const float4* p1 = (const float4*)(g_part + (size_t)s1 * H_DIM);
    float4* o = (float4*)(out + (size_t)t * H_DIM);
    for (int i = threadIdx.x; i < H_DIM / 4; i += blockDim.x) {
        float4 a = p0[i], b = p1[i];
        o[i] = make_float4(a.x + b.x, a.y + b.y, a.z + b.z, a.w + b.w);
    }
}

// ---------------------------------------------------------------------------
extern "C" void kernel_launch(void* const* d_in, const int* in_sizes, int n_in,
                              void* d_out, int out_size) {
    const float* hidden   = (const float*)d_in[0];
    const float* router_w = (const float*)d_in[1];
    const float* gate_w   = (const float*)d_in[2];
    const float* up_w     = (const float*)d_in[3];
    const float* down_w   = (const float*)d_in[4];
    float* out = (float*)d_out;

    cudaFuncSetAttribute(gateup_mma, cudaFuncAttributeMaxDynamicSharedMemorySize, GU_SMEM);
    cudaFuncSetAttribute(down_mma,   cudaFuncAttributeMaxDynamicSharedMemorySize, DN_SMEM);

    __half* gate_h; cudaGetSymbolAddress((void**)&gate_h, g_gate_h);
    __half* up_h;   cudaGetSymbolAddress((void**)&up_h,   g_up_h);
    __half* down_h; cudaGetSymbolAddress((void**)&down_h, g_down_h);
    __half* xh;     cudaGetSymbolAddress((void**)&xh,     g_xh);

    // weight + activation conversion (memory-bound)
    cvt_kernel<<<WELEM/8/256, 256>>>(gate_w, gate_h, WELEM/8);
    cvt_kernel<<<WELEM/8/256, 256>>>(up_w,   up_h,   WELEM/8);
    cvt_kernel<<<WELEM/8/256, 256>>>(down_w, down_h, WELEM/8);
    cvt_kernel<<<T_TOK*H_DIM/8/256, 256>>>(hidden, xh, T_TOK*H_DIM/8);

    router_kernel<<<T_TOK, 512>>>(hidden, router_w);
    build_kernel<<<1, 512>>>();

    dim3 gridG(I_DIM / 64, NPAIR / 128, E_NUM);
    gateup_mma<<<gridG, 256, GU_SMEM>>>(xh);

    dim3 gridD(H_DIM / 128, NPAIR / 128, E_NUM);
    down_mma<<<gridD, 256, DN_SMEM>>>();

    combine_kernel<<<T_TOK, 256>>>(out);
}

// round 6
// speedup vs baseline: 1.0371x; 1.0371x over previous
#include <cuda_runtime.h>
#include <cuda_fp16.h>
#include <math.h>
#include <cstdint>

// Problem constants
#define T_TOK   2048
#define H_DIM   1024
#define E_NUM   16
#define I_DIM   1024
#define NPAIR   (T_TOK*2)
#define WELEM   (E_NUM*I_DIM*H_DIM)   // 16,777,216 per weight tensor

// Scratch (device globals)
__device__ __half g_gate_h[WELEM];
__device__ __half g_up_h  [WELEM];
__device__ __half g_down_h[WELEM];
__device__ __half g_xh    [T_TOK * H_DIM];
__device__ __half g_act   [NPAIR * I_DIM];
__device__ float  g_part  [NPAIR * H_DIM];
__device__ int    g_expert_of[NPAIR];
__device__ float  g_weight_of[NPAIR];
__device__ int    g_base [E_NUM];
__device__ int    g_count[E_NUM];
__device__ int    g_pair_token[NPAIR];
__device__ float  g_pair_w   [NPAIR];
__device__ int    g_slot_of  [NPAIR];

// ---------------------------------------------------------------------------
// helpers
// ---------------------------------------------------------------------------
__device__ __forceinline__ uint32_t smem_u32(const void* p) {
    uint32_t a;
    asm("{ .reg .u64 t; cvta.to.shared.u64 t, %1; cvt.u32.u64 %0, t; }" : "=r"(a) : "l"(p));
    return a;
}
__device__ __forceinline__ void ldsm_x4(uint32_t* r, uint32_t addr) {
    asm volatile("ldmatrix.sync.aligned.m8n8.x4.shared.b16 {%0,%1,%2,%3}, [%4];"
                 : "=r"(r[0]), "=r"(r[1]), "=r"(r[2]), "=r"(r[3]) : "r"(addr));
}
__device__ __forceinline__ void mma16816(float* c, const uint32_t* a, const uint32_t* b) {
    asm volatile("mma.sync.aligned.m16n8k16.row.col.f32.f16.f16.f32 "
                 "{%0,%1,%2,%3}, {%4,%5,%6,%7}, {%8,%9}, {%0,%1,%2,%3};"
                 : "+f"(c[0]), "+f"(c[1]), "+f"(c[2]), "+f"(c[3])
                 : "r"(a[0]), "r"(a[1]), "r"(a[2]), "r"(a[3]), "r"(b[0]), "r"(b[1]));
}
__device__ __forceinline__ uint32_t packh2(float x, float y) {
    __half2 h = __floats2half2_rn(x, y);
    return *(uint32_t*)&h;
}
__device__ __forceinline__ void cp16(uint32_t smem_dst, const void* gmem_src) {
    asm volatile("cp.async.cg.shared.global [%0], [%1], 16;"
                 :: "r"(smem_dst), "l"(gmem_src));
}
#define CP_COMMIT() asm volatile("cp.async.commit_group;" ::: "memory")
#define CP_WAIT2()  asm volatile("cp.async.wait_group 2;" ::: "memory")

#define PITCH 40
#define ROWB  80
#define STAGES 4

// ---------------------------------------------------------------------------
// 0) fused fp32 -> fp16 conversion: all 3 weight tensors + x, grid-stride
// ---------------------------------------------------------------------------
#define N8_W   (WELEM/8)
#define N8_X   (T_TOK*H_DIM/8)
#define N8_TOT (3*N8_W + N8_X)

__global__ void cvt_all_kernel(const float* __restrict__ gw,
                               const float* __restrict__ uw,
                               const float* __restrict__ dw,
                               const float* __restrict__ x,
                               __half* __restrict__ gh, __half* __restrict__ uh,
                               __half* __restrict__ dh, __half* __restrict__ xh) {
    for (int i = blockIdx.x * blockDim.x + threadIdx.x; i < N8_TOT;
         i += gridDim.x * blockDim.x) {
        const float* src; __half* dst; int j;
        if (i < N8_W)            { src = gw; dst = gh; j = i; }
        else if (i < 2*N8_W)     { src = uw; dst = uh; j = i - N8_W; }
        else if (i < 3*N8_W)     { src = dw; dst = dh; j = i - 2*N8_W; }
        else                     { src = x;  dst = xh; j = i - 3*N8_W; }
        float4 a = ((const float4*)src)[2*j];
        float4 b = ((const float4*)src)[2*j+1];
        uint4 o;
        o.x = packh2(a.x, a.y); o.y = packh2(a.z, a.w);
        o.z = packh2(b.x, b.y); o.w = packh2(b.z, b.w);
        ((uint4*)dst)[j] = o;
    }
}

// ---------------------------------------------------------------------------
// 1) Router
// ---------------------------------------------------------------------------
__global__ void router_kernel(const float* __restrict__ x,
                              const float* __restrict__ rw) {
    int t = blockIdx.x;
    int warp = threadIdx.x >> 5, lane = threadIdx.x & 31;
    __shared__ float logits[E_NUM];
    const float* xr = x + (size_t)t * H_DIM;
    const float* wr = rw + (size_t)warp * H_DIM;
    float s = 0.f;
    #pragma unroll 4
    for (int h = lane; h < H_DIM; h += 32) s += xr[h] * wr[h];
    #pragma unroll
    for (int o = 16; o; o >>= 1) s += __shfl_xor_sync(0xffffffffu, s, o);
    if (lane == 0) logits[warp] = s;
    __syncthreads();
    if (threadIdx.x == 0) {
        float sc[E_NUM];
        #pragma unroll
        for (int e = 0; e < E_NUM; e++) sc[e] = 1.f / (1.f + expf(-logits[e]));
        int i0 = 0;
        #pragma unroll
        for (int e = 1; e < E_NUM; e++) if (sc[e] > sc[i0]) i0 = e;
        int i1 = -1;
        #pragma unroll
        for (int e = 0; e < E_NUM; e++) {
            if (e == i0) continue;
            if (i1 < 0 || sc[e] > sc[i1]) i1 = e;
        }
        float w0 = sc[i0], w1 = sc[i1];
        float inv = 1.f / (w0 + w1 + 1e-20f);
        g_expert_of[2*t]   = i0;  g_weight_of[2*t]   = w0 * inv;
        g_expert_of[2*t+1] = i1;  g_weight_of[2*t+1] = w1 * inv;
    }
}

// ---------------------------------------------------------------------------
// 2) Build expert-sorted pair lists
// ---------------------------------------------------------------------------
__global__ void build_kernel() {
    __shared__ unsigned char eid[NPAIR];
    __shared__ int cnt[E_NUM], bs[E_NUM];
    int tid = threadIdx.x;
    for (int p = tid; p < NPAIR; p += blockDim.x)
        eid[p] = (unsigned char)g_expert_of[p];
    __syncthreads();
    if (tid < E_NUM) {
        int c = 0;
        for (int p = 0; p < NPAIR; p++) c += (eid[p] == tid);
        cnt[tid] = c;
    }
    __syncthreads();
    if (tid == 0) {
        int acc = 0;
        for (int e = 0; e < E_NUM; e++) { bs[e] = acc; acc += cnt[e]; }
    }
    __syncthreads();
    int w = tid >> 5, lane = tid & 31;
    if (w < E_NUM) {
        int e = w, pos = bs[e];
        for (int p0 = 0; p0 < NPAIR; p0 += 32) {
            int p = p0 + lane;
            bool m = (eid[p] == e);
            unsigned mask = __ballot_sync(0xffffffffu, m);
            if (m) {
                int s = pos + __popc(mask & ((1u << lane) - 1u));
                g_pair_token[s] = p >> 1;
                g_pair_w[s]     = g_weight_of[p];
                g_slot_of[p]    = s;
            }
            pos += __popc(mask);
        }
    }
    if (tid < E_NUM) { g_base[tid] = bs[tid]; g_count[tid] = cnt[tid]; }
}

// ---------------------------------------------------------------------------
// 3) gateup: 4-stage cp.async fp16 pipeline, 2 CTAs/SM
// ---------------------------------------------------------------------------
#define GU_ASTG 10240
#define GU_BSTG 5120
#define GU_OFFA 0
#define GU_OFFG (4*GU_ASTG)
#define GU_OFFU (GU_OFFG + 4*GU_BSTG)
#define GU_SMEM (GU_OFFU + 4*GU_BSTG)

__global__ __launch_bounds__(256, 2)
void gateup_mma(const __half* __restrict__ xh) {
    int e  = blockIdx.z;
    int m0 = blockIdx.y * 128;
    int n0 = blockIdx.x * 64;
    int cnt = g_count[e];
    if (m0 >= cnt) return;
    int bse = g_base[e];

    extern __shared__ char dsm[];
    uint32_t sb = smem_u32(dsm);
    __shared__ int   tok_s[128];
    __shared__ float wrow_s[128];

    int tid = threadIdx.x, lane = tid & 31, wid = tid >> 5;
    if (tid < 128) {
        int m = m0 + tid;
        bool v = m < cnt;
        int mc = v ? m : (cnt - 1);
        tok_s[tid]  = g_pair_token[bse + mc];
        wrow_s[tid] = v ? g_pair_w[bse + m] : 0.f;
    }
    __syncthreads();

    const __half* Gh = g_gate_h + ((size_t)e << 20) + (size_t)n0 * H_DIM;
    const __half* Uh = g_up_h   + ((size_t)e << 20) + (size_t)n0 * H_DIM;

    int wm = wid & 3, wn = wid >> 2;
    int m_base = wm * 32, n_base = wn * 32;

    uint32_t addrA[2];
    #pragma unroll
    for (int i = 0; i < 2; i++)
        addrA[i] = sb + GU_OFFA + (uint32_t)((m_base + i*16 + (lane & 15)) * ROWB) + ((lane >> 4) * 16);
    uint32_t addrBg[2], addrBu[2];
    #pragma unroll
    for (int jj = 0; jj < 2; jj++) {
        uint32_t row = (uint32_t)(n_base + jj*16 + (lane & 7) + (((lane >> 4) & 1) << 3));
        uint32_t off = row * ROWB + (((lane >> 3) & 1) * 16);
        addrBg[jj] = sb + GU_OFFG + off;
        addrBu[jj] = sb + GU_OFFU + off;
    }

    int ar0 = tid >> 2, ac0 = tid & 3;
    int br  = tid >> 2, bc  = tid & 3;

    float cg[2][4][4] = {}, cu[2][4][4] = {};

    #pragma unroll
    for (int s = 0; s < STAGES-1; s++) {
        int k0 = s * 32;
        uint32_t dA = sb + GU_OFFA + s * GU_ASTG;
        #pragma unroll
        for (int j = 0; j < 2; j++) {
            int r = ar0 + j*64;
            cp16(dA + r*ROWB + ac0*16, xh + (size_t)tok_s[r] * H_DIM + k0 + ac0*8);
        }
        cp16(sb + GU_OFFG + s*GU_BSTG + br*ROWB + bc*16, Gh + (size_t)br * H_DIM + k0 + bc*8);
        cp16(sb + GU_OFFU + s*GU_BSTG + br*ROWB + bc*16, Uh + (size_t)br * H_DIM + k0 + bc*8);
        CP_COMMIT();
    }

    const int NIT = H_DIM / 32;
    for (int it = 0; it < NIT; it++) {
        CP_WAIT2();
        __syncthreads();
        int cur = it & 3;
        uint32_t offA = (uint32_t)cur * GU_ASTG;
        uint32_t offB = (uint32_t)cur * GU_BSTG;
        #pragma unroll
        for (int ks = 0; ks < 2; ks++) {
            uint32_t a[2][4];
            #pragma unroll
            for (int i = 0; i < 2; i++) ldsm_x4(a[i], addrA[i] + offA + ks*32);
            uint32_t bg[2][4], bu[2][4];
            #pragma unroll
            for (int jj = 0; jj < 2; jj++) {
                ldsm_x4(bg[jj], addrBg[jj] + offB + ks*32);
                ldsm_x4(bu[jj], addrBu[jj] + offB + ks*32);
            }
            #pragma unroll
            for (int i = 0; i < 2; i++)
                #pragma unroll
                for (int jj = 0; jj < 2; jj++) {
                    mma16816(cg[i][2*jj+0], a[i], &bg[jj][0]);
                    mma16816(cg[i][2*jj+1], a[i], &bg[jj][2]);
                    mma16816(cu[i][2*jj+0], a[i], &bu[jj][0]);
                    mma16816(cu[i][2*jj+1], a[i], &bu[jj][2]);
                }
        }
        if (it + STAGES-1 < NIT) {
            int s = (it + STAGES-1) & 3;
            int k0 = (it + STAGES-1) * 32;
            uint32_t dA = sb + GU_OFFA + s * GU_ASTG;
            #pragma unroll
            for (int j = 0; j < 2; j++) {
                int r = ar0 + j*64;
                cp16(dA + r*ROWB + ac0*16, xh + (size_t)tok_s[r] * H_DIM + k0 + ac0*8);
            }
            cp16(sb + GU_OFFG + s*GU_BSTG + br*ROWB + bc*16, Gh + (size_t)br * H_DIM + k0 + bc*8);
            cp16(sb + GU_OFFU + s*GU_BSTG + br*ROWB + bc*16, Uh + (size_t)br * H_DIM + k0 + bc*8);
        }
        CP_COMMIT();
    }

    #pragma unroll
    for (int i = 0; i < 2; i++) {
        #pragma unroll
        for (int h = 0; h < 2; h++) {
            int ml = m_base + i*16 + h*8 + (lane >> 2);
            int m  = m0 + ml;
            if (m >= cnt) continue;
            float w = wrow_s[ml];
            __half* arow = g_act + (size_t)(bse + m) * I_DIM + n0;
            #pragma unroll
            for (int j = 0; j < 4; j++) {
                int nl = n_base + j*8 + 2*(lane & 3);
                float g0 = cg[i][j][h*2+0], g1 = cg[i][j][h*2+1];
                float u0 = cu[i][j][h*2+0], u1 = cu[i][j][h*2+1];
                float a0 = w * (g0 / (1.f + __expf(-g0))) * u0;
                float a1 = w * (g1 / (1.f + __expf(-g1))) * u1;
                *(uint32_t*)&arow[nl] = packh2(a0, a1);
            }
        }
    }
}

// ---------------------------------------------------------------------------
// 4) down: 4-stage cp.async fp16 pipeline, 2 CTAs/SM -> g_part
// ---------------------------------------------------------------------------
#define DN_STG  10240
#define DN_OFFA 0
#define DN_OFFB (4*DN_STG)
#define DN_SMEM (8*DN_STG)

__global__ __launch_bounds__(256, 2)
void down_mma() {
    int e  = blockIdx.z;
    int m0 = blockIdx.y * 128;
    int n0 = blockIdx.x * 128;
    int cnt = g_count[e];
    if (m0 >= cnt) return;
    int bse = g_base[e];

    extern __shared__ char dsm[];
    uint32_t sb = smem_u32(dsm);

    int tid = threadIdx.x, lane = tid & 31, wid = tid >> 5;
    int mlim = cnt - m0;

    const __half* Dh = g_down_h + ((size_t)e << 20) + (size_t)n0 * I_DIM;

    int wm = wid & 3, wn = wid >> 2;
    int m_base = wm * 32, n_base = wn * 64;

    uint32_t addrA[2];
    #pragma unroll
    for (int i = 0; i < 2; i++)
        addrA[i] = sb + DN_OFFA + (uint32_t)((m_base + i*16 + (lane & 15)) * ROWB) + ((lane >> 4) * 16);
    uint32_t addrB[4];
    #pragma unroll
    for (int jj = 0; jj < 4; jj++) {
        uint32_t row = (uint32_t)(n_base + jj*16 + (lane & 7) + (((lane >> 4) & 1) << 3));
        addrB[jj] = sb + DN_OFFB + row * ROWB + (((lane >> 3) & 1) * 16);
    }

    int lr = tid >> 2, lc = tid & 3;
    int ra0 = (lr      < mlim) ? lr      : (mlim - 1);
    int ra1 = (lr + 64 < mlim) ? lr + 64 : (mlim - 1);
    const __half* A0 = g_act + (size_t)(bse + m0 + ra0) * I_DIM;
    const __half* A1 = g_act + (size_t)(bse + m0 + ra1) * I_DIM;

    float cc[2][8][4] = {};

    #pragma unroll
    for (int s = 0; s < STAGES-1; s++) {
        int k0 = s * 32;
        uint32_t dA = sb + DN_OFFA + s * DN_STG;
        uint32_t dB = sb + DN_OFFB + s * DN_STG;
        cp16(dA + lr*ROWB        + lc*16, A0 + k0 + lc*8);
        cp16(dA + (lr+64)*ROWB   + lc*16, A1 + k0 + lc*8);
        cp16(dB + lr*ROWB        + lc*16, Dh + (size_t)lr       * I_DIM + k0 + lc*8);
        cp16(dB + (lr+64)*ROWB   + lc*16, Dh + (size_t)(lr+64)  * I_DIM + k0 + lc*8);
        CP_COMMIT();
    }

    const int NIT = I_DIM / 32;
    for (int it = 0; it < NIT; it++) {
        CP_WAIT2();
        __syncthreads();
        int cur = it & 3;
        uint32_t offA = (uint32_t)cur * DN_STG;
        uint32_t offB = (uint32_t)cur * DN_STG;
        #pragma unroll
        for (int ks = 0; ks < 2; ks++) {
            uint32_t a[2][4];
            #pragma unroll
            for (int i = 0; i < 2; i++) ldsm_x4(a[i], addrA[i] + offA + ks*32);
            uint32_t b[4][4];
            #pragma unroll
            for (int jj = 0; jj < 4; jj++) ldsm_x4(b[jj], addrB[jj] + offB + ks*32);
            #pragma unroll
            for (int i = 0; i < 2; i++)
                #pragma unroll
                for (int jj = 0; jj < 4; jj++) {
                    mma16816(cc[i][2*jj+0], a[i], &b[jj][0]);
                    mma16816(cc[i][2*jj+1], a[i], &b[jj][2]);
                }
        }
        if (it + STAGES-1 < NIT) {
            int s = (it + STAGES-1) & 3;
            int k0 = (it + STAGES-1) * 32;
            uint32_t dA = sb + DN_OFFA + s * DN_STG;
            uint32_t dB = sb + DN_OFFB + s * DN_STG;
            cp16(dA + lr*ROWB      + lc*16, A0 + k0 + lc*8);
            cp16(dA + (lr+64)*ROWB + lc*16, A1 + k0 + lc*8);
            cp16(dB + lr*ROWB      + lc*16, Dh + (size_t)lr      * I_DIM + k0 + lc*8);
            cp16(dB + (lr+64)*ROWB + lc*16, Dh + (size_t)(lr+64) * I_DIM + k0 + lc*8);
        }
        CP_COMMIT();
    }

    #pragma unroll
    for (int i = 0; i < 2; i++) {
        #pragma unroll
        for (int h = 0; h < 2; h++) {
            int ml = m_base + i*16 + h*8 + (lane >> 2);
            int m  = m0 + ml;
            if (m >= cnt) continue;
            float* prow = g_part + (size_t)(bse + m) * H_DIM + n0;
            #pragma unroll
            for (int j = 0; j < 8; j++) {
                int nl = n_base + j*8 + 2*(lane & 3);
                *(float2*)&prow[nl] = make_float2(cc[i][j][h*2+0], cc[i][j][h*2+1]);
            }
        }
    }
}

// ---------------------------------------------------------------------------
// 5) Combine
// ---------------------------------------------------------------------------
__global__ void combine_kernel(float* __restrict__ out) {
    int t = blockIdx.x;
    int s0 = g_slot_of[2*t], s1 = g_slot_of[2*t + 1];
    const float4* p0 = (const float4*)(g_part + (size_t)s0 * H_DIM);
    const float4* p1 = (const float4*)(g_part + (size_t)s1 * H_DIM);
    float4* o = (float4*)(out + (size_t)t * H_DIM);
    for (int i = threadIdx.x; i < H_DIM / 4; i += blockDim.x) {
        float4 a = p0[i], b = p1[i];
        o[i] = make_float4(a.x + b.x, a.y + b.y, a.z + b.z, a.w + b.w);
    }
}

// ---------------------------------------------------------------------------
extern "C" void kernel_launch(void* const* d_in, const int* in_sizes, int n_in,
                              void* d_out, int out_size) {
    const float* hidden   = (const float*)d_in[0];
    const float* router_w = (const float*)d_in[1];
    const float* gate_w   = (const float*)d_in[2];
    const float* up_w     = (const float*)d_in[3];
    const float* down_w   = (const float*)d_in[4];
    float* out = (float*)d_out;

    cudaFuncSetAttribute(gateup_mma, cudaFuncAttributeMaxDynamicSharedMemorySize, GU_SMEM);
    cudaFuncSetAttribute(down_mma,   cudaFuncAttributeMaxDynamicSharedMemorySize, DN_SMEM);
    cudaFuncSetAttribute(gateup_mma, cudaFuncAttributePreferredSharedMemoryCarveout,
                         cudaSharedmemCarveoutMaxShared);
    cudaFuncSetAttribute(down_mma,   cudaFuncAttributePreferredSharedMemoryCarveout,
                         cudaSharedmemCarveoutMaxShared);

    __half* gate_h; cudaGetSymbolAddress((void**)&gate_h, g_gate_h);
    __half* up_h;   cudaGetSymbolAddress((void**)&up_h,   g_up_h);
    __half* down_h; cudaGetSymbolAddress((void**)&down_h, g_down_h);
    __half* xh;     cudaGetSymbolAddress((void**)&xh,     g_xh);

    cvt_all_kernel<<<2048, 256>>>(gate_w, up_w, down_w, hidden,
                                  gate_h, up_h, down_h, xh);

    router_kernel<<<T_TOK, 512>>>(hidden, router_w);
    build_kernel<<<1, 512>>>();

    dim3 gridG(I_DIM / 64, NPAIR / 128, E_NUM);
    gateup_mma<<<gridG, 256, GU_SMEM>>>(xh);

    dim3 gridD(H_DIM / 128, NPAIR / 128, E_NUM);
    down_mma<<<gridD, 256, DN_SMEM>>>();

    combine_kernel<<<T_TOK, 256>>>(out);
}

// round 7
// speedup vs baseline: 1.0625x; 1.0245x over previous
#include <cuda_runtime.h>
#include <cuda_fp16.h>
#include <math.h>
#include <cstdint>

// Problem constants
#define T_TOK   2048
#define H_DIM   1024
#define E_NUM   16
#define I_DIM   1024
#define NPAIR   (T_TOK*2)
#define WELEM   (E_NUM*I_DIM*H_DIM)

// Scratch (device globals)
__device__ __half g_gate_h[WELEM];
__device__ __half g_up_h  [WELEM];
__device__ __half g_down_h[WELEM];
__device__ __half g_xh    [T_TOK * H_DIM];
__device__ __half g_act   [NPAIR * I_DIM];
__device__ float  g_part  [NPAIR * H_DIM];
__device__ int    g_expert_of[NPAIR];
__device__ float  g_weight_of[NPAIR];
__device__ int    g_base [E_NUM];
__device__ int    g_count[E_NUM];
__device__ int    g_pair_token[NPAIR];
__device__ float  g_pair_w   [NPAIR];
__device__ int    g_slot_of  [NPAIR];

// ---------------------------------------------------------------------------
// helpers
// ---------------------------------------------------------------------------
__device__ __forceinline__ uint32_t smem_u32(const void* p) {
    uint32_t a;
    asm("{ .reg .u64 t; cvta.to.shared.u64 t, %1; cvt.u32.u64 %0, t; }" : "=r"(a) : "l"(p));
    return a;
}
__device__ __forceinline__ void ldsm_x4(uint32_t* r, uint32_t addr) {
    asm volatile("ldmatrix.sync.aligned.m8n8.x4.shared.b16 {%0,%1,%2,%3}, [%4];"
                 : "=r"(r[0]), "=r"(r[1]), "=r"(r[2]), "=r"(r[3]) : "r"(addr));
}
__device__ __forceinline__ void mma16816(float* c, const uint32_t* a, const uint32_t* b) {
    asm volatile("mma.sync.aligned.m16n8k16.row.col.f32.f16.f16.f32 "
                 "{%0,%1,%2,%3}, {%4,%5,%6,%7}, {%8,%9}, {%0,%1,%2,%3};"
                 : "+f"(c[0]), "+f"(c[1]), "+f"(c[2]), "+f"(c[3])
                 : "r"(a[0]), "r"(a[1]), "r"(a[2]), "r"(a[3]), "r"(b[0]), "r"(b[1]));
}
__device__ __forceinline__ uint32_t packh2(float x, float y) {
    __half2 h = __floats2half2_rn(x, y);
    return *(uint32_t*)&h;
}
__device__ __forceinline__ void cp16(uint32_t smem_dst, const void* gmem_src) {
    asm volatile("cp.async.cg.shared.global [%0], [%1], 16;"
                 :: "r"(smem_dst), "l"(gmem_src));
}
#define CP_COMMIT() asm volatile("cp.async.commit_group;" ::: "memory")
#define CP_WAIT3()  asm volatile("cp.async.wait_group 3;" ::: "memory")

#define PITCH 40
#define ROWB  80
#define STAGES 5

// ---------------------------------------------------------------------------
// 0) fused fp32 -> fp16 conversion, one 8-pack per thread (max MLP)
// ---------------------------------------------------------------------------
#define N8_W   (WELEM/8)
#define N8_X   (T_TOK*H_DIM/8)
#define N8_TOT (3*N8_W + N8_X)

__global__ void cvt_all_kernel(const float* __restrict__ gw,
                               const float* __restrict__ uw,
                               const float* __restrict__ dw,
                               const float* __restrict__ x,
                               __half* __restrict__ gh, __half* __restrict__ uh,
                               __half* __restrict__ dh, __half* __restrict__ xh) {
    int i = blockIdx.x * blockDim.x + threadIdx.x;
    if (i >= N8_TOT) return;
    const float* src; __half* dst; int j;
    if (i < N8_W)            { src = gw; dst = gh; j = i; }
    else if (i < 2*N8_W)     { src = uw; dst = uh; j = i - N8_W; }
    else if (i < 3*N8_W)     { src = dw; dst = dh; j = i - 2*N8_W; }
    else                     { src = x;  dst = xh; j = i - 3*N8_W; }
    float4 a = ((const float4*)src)[2*j];
    float4 b = ((const float4*)src)[2*j+1];
    uint4 o;
    o.x = packh2(a.x, a.y); o.y = packh2(a.z, a.w);
    o.z = packh2(b.x, b.y); o.w = packh2(b.z, b.w);
    ((uint4*)dst)[j] = o;
}

// ---------------------------------------------------------------------------
// 1) Router
// ---------------------------------------------------------------------------
__global__ void router_kernel(const float* __restrict__ x,
                              const float* __restrict__ rw) {
    int t = blockIdx.x;
    int warp = threadIdx.x >> 5, lane = threadIdx.x & 31;
    __shared__ float logits[E_NUM];
    const float* xr = x + (size_t)t * H_DIM;
    const float* wr = rw + (size_t)warp * H_DIM;
    float s = 0.f;
    #pragma unroll 4
    for (int h = lane; h < H_DIM; h += 32) s += xr[h] * wr[h];
    #pragma unroll
    for (int o = 16; o; o >>= 1) s += __shfl_xor_sync(0xffffffffu, s, o);
    if (lane == 0) logits[warp] = s;
    __syncthreads();
    if (threadIdx.x == 0) {
        float sc[E_NUM];
        #pragma unroll
        for (int e = 0; e < E_NUM; e++) sc[e] = 1.f / (1.f + expf(-logits[e]));
        int i0 = 0;
        #pragma unroll
        for (int e = 1; e < E_NUM; e++) if (sc[e] > sc[i0]) i0 = e;
        int i1 = -1;
        #pragma unroll
        for (int e = 0; e < E_NUM; e++) {
            if (e == i0) continue;
            if (i1 < 0 || sc[e] > sc[i1]) i1 = e;
        }
        float w0 = sc[i0], w1 = sc[i1];
        float inv = 1.f / (w0 + w1 + 1e-20f);
        g_expert_of[2*t]   = i0;  g_weight_of[2*t]   = w0 * inv;
        g_expert_of[2*t+1] = i1;  g_weight_of[2*t+1] = w1 * inv;
    }
}

// ---------------------------------------------------------------------------
// 2) Build expert-sorted pair lists
// ---------------------------------------------------------------------------
__global__ void build_kernel() {
    __shared__ unsigned char eid[NPAIR];
    __shared__ int cnt[E_NUM], bs[E_NUM];
    int tid = threadIdx.x;
    for (int p = tid; p < NPAIR; p += blockDim.x)
        eid[p] = (unsigned char)g_expert_of[p];
    __syncthreads();
    if (tid < E_NUM) {
        int c = 0;
        for (int p = 0; p < NPAIR; p++) c += (eid[p] == tid);
        cnt[tid] = c;
    }
    __syncthreads();
    if (tid == 0) {
        int acc = 0;
        for (int e = 0; e < E_NUM; e++) { bs[e] = acc; acc += cnt[e]; }
    }
    __syncthreads();
    int w = tid >> 5, lane = tid & 31;
    if (w < E_NUM) {
        int e = w, pos = bs[e];
        for (int p0 = 0; p0 < NPAIR; p0 += 32) {
            int p = p0 + lane;
            bool m = (eid[p] == e);
            unsigned mask = __ballot_sync(0xffffffffu, m);
            if (m) {
                int s = pos + __popc(mask & ((1u << lane) - 1u));
                g_pair_token[s] = p >> 1;
                g_pair_w[s]     = g_weight_of[p];
                g_slot_of[p]    = s;
            }
            pos += __popc(mask);
        }
    }
    if (tid < E_NUM) { g_base[tid] = bs[tid]; g_count[tid] = cnt[tid]; }
}

// ---------------------------------------------------------------------------
// 3) gateup: 5-stage cp.async fp16 pipeline, early issue, 2 CTAs/SM
// ---------------------------------------------------------------------------
#define GU_ASTG 10240
#define GU_BSTG 5120
#define GU_OFFA 0
#define GU_OFFG (STAGES*GU_ASTG)
#define GU_OFFU (GU_OFFG + STAGES*GU_BSTG)
#define GU_SMEM (GU_OFFU + STAGES*GU_BSTG)

__global__ __launch_bounds__(256, 2)
void gateup_mma(const __half* __restrict__ xh) {
    int e  = blockIdx.z;
    int m0 = blockIdx.y * 128;
    int n0 = blockIdx.x * 64;
    int cnt = g_count[e];
    if (m0 >= cnt) return;
    int bse = g_base[e];

    extern __shared__ char dsm[];
    uint32_t sb = smem_u32(dsm);
    __shared__ int   tok_s[128];
    __shared__ float wrow_s[128];

    int tid = threadIdx.x, lane = tid & 31, wid = tid >> 5;
    if (tid < 128) {
        int m = m0 + tid;
        bool v = m < cnt;
        int mc = v ? m : (cnt - 1);
        tok_s[tid]  = g_pair_token[bse + mc];
        wrow_s[tid] = v ? g_pair_w[bse + m] : 0.f;
    }
    __syncthreads();

    const __half* Gh = g_gate_h + ((size_t)e << 20) + (size_t)n0 * H_DIM;
    const __half* Uh = g_up_h   + ((size_t)e << 20) + (size_t)n0 * H_DIM;

    int wm = wid & 3, wn = wid >> 2;
    int m_base = wm * 32, n_base = wn * 32;

    uint32_t addrA[2];
    #pragma unroll
    for (int i = 0; i < 2; i++)
        addrA[i] = sb + GU_OFFA + (uint32_t)((m_base + i*16 + (lane & 15)) * ROWB) + ((lane >> 4) * 16);
    uint32_t addrBg[2], addrBu[2];
    #pragma unroll
    for (int jj = 0; jj < 2; jj++) {
        uint32_t row = (uint32_t)(n_base + jj*16 + (lane & 7) + (((lane >> 4) & 1) << 3));
        uint32_t off = row * ROWB + (((lane >> 3) & 1) * 16);
        addrBg[jj] = sb + GU_OFFG + off;
        addrBu[jj] = sb + GU_OFFU + off;
    }

    int ar0 = tid >> 2, ac0 = tid & 3;
    int br  = tid >> 2, bc  = tid & 3;

    float cg[2][4][4] = {}, cu[2][4][4] = {};

    // prologue: fill stages 0..3
    #pragma unroll
    for (int s = 0; s < STAGES-1; s++) {
        int k0 = s * 32;
        uint32_t dA = sb + GU_OFFA + s * GU_ASTG;
        #pragma unroll
        for (int j = 0; j < 2; j++) {
            int r = ar0 + j*64;
            cp16(dA + r*ROWB + ac0*16, xh + (size_t)tok_s[r] * H_DIM + k0 + ac0*8);
        }
        cp16(sb + GU_OFFG + s*GU_BSTG + br*ROWB + bc*16, Gh + (size_t)br * H_DIM + k0 + bc*8);
        cp16(sb + GU_OFFU + s*GU_BSTG + br*ROWB + bc*16, Uh + (size_t)br * H_DIM + k0 + bc*8);
        CP_COMMIT();
    }

    const int NIT = H_DIM / 32;
    int cons = 0, fill = STAGES - 1;
    for (int it = 0; it < NIT; it++) {
        CP_WAIT3();
        __syncthreads();
        // early issue: fill stage (it+4) into buffer freed at it-1
        if (it + STAGES-1 < NIT) {
            int k0 = (it + STAGES-1) * 32;
            uint32_t dA = sb + GU_OFFA + fill * GU_ASTG;
            #pragma unroll
            for (int j = 0; j < 2; j++) {
                int r = ar0 + j*64;
                cp16(dA + r*ROWB + ac0*16, xh + (size_t)tok_s[r] * H_DIM + k0 + ac0*8);
            }
            cp16(sb + GU_OFFG + fill*GU_BSTG + br*ROWB + bc*16, Gh + (size_t)br * H_DIM + k0 + bc*8);
            cp16(sb + GU_OFFU + fill*GU_BSTG + br*ROWB + bc*16, Uh + (size_t)br * H_DIM + k0 + bc*8);
        }
        CP_COMMIT();

        uint32_t offA = (uint32_t)cons * GU_ASTG;
        uint32_t offB = (uint32_t)cons * GU_BSTG;
        #pragma unroll
        for (int ks = 0; ks < 2; ks++) {
            uint32_t a[2][4];
            #pragma unroll
            for (int i = 0; i < 2; i++) ldsm_x4(a[i], addrA[i] + offA + ks*32);
            uint32_t bg[2][4], bu[2][4];
            #pragma unroll
            for (int jj = 0; jj < 2; jj++) {
                ldsm_x4(bg[jj], addrBg[jj] + offB + ks*32);
                ldsm_x4(bu[jj], addrBu[jj] + offB + ks*32);
            }
            #pragma unroll
            for (int i = 0; i < 2; i++)
                #pragma unroll
                for (int jj = 0; jj < 2; jj++) {
                    mma16816(cg[i][2*jj+0], a[i], &bg[jj][0]);
                    mma16816(cg[i][2*jj+1], a[i], &bg[jj][2]);
                    mma16816(cu[i][2*jj+0], a[i], &bu[jj][0]);
                    mma16816(cu[i][2*jj+1], a[i], &bu[jj][2]);
                }
        }
        if (++cons == STAGES) cons = 0;
        if (++fill == STAGES) fill = 0;
    }

    #pragma unroll
    for (int i = 0; i < 2; i++) {
        #pragma unroll
        for (int h = 0; h < 2; h++) {
            int ml = m_base + i*16 + h*8 + (lane >> 2);
            int m  = m0 + ml;
            if (m >= cnt) continue;
            float w = wrow_s[ml];
            __half* arow = g_act + (size_t)(bse + m) * I_DIM + n0;
            #pragma unroll
            for (int j = 0; j < 4; j++) {
                int nl = n_base + j*8 + 2*(lane & 3);
                float g0 = cg[i][j][h*2+0], g1 = cg[i][j][h*2+1];
                float u0 = cu[i][j][h*2+0], u1 = cu[i][j][h*2+1];
                float a0 = w * (g0 / (1.f + __expf(-g0))) * u0;
                float a1 = w * (g1 / (1.f + __expf(-g1))) * u1;
                *(uint32_t*)&arow[nl] = packh2(a0, a1);
            }
        }
    }
}

// ---------------------------------------------------------------------------
// 4) down: 5-stage cp.async fp16 pipeline, early issue, 2 CTAs/SM -> g_part
// ---------------------------------------------------------------------------
#define DN_STG  10240
#define DN_OFFA 0
#define DN_OFFB (STAGES*DN_STG)
#define DN_SMEM (2*STAGES*DN_STG)

__global__ __launch_bounds__(256, 2)
void down_mma() {
    int e  = blockIdx.z;
    int m0 = blockIdx.y * 128;
    int n0 = blockIdx.x * 128;
    int cnt = g_count[e];
    if (m0 >= cnt) return;
    int bse = g_base[e];

    extern __shared__ char dsm[];
    uint32_t sb = smem_u32(dsm);

    int tid = threadIdx.x, lane = tid & 31, wid = tid >> 5;
    int mlim = cnt - m0;

    const __half* Dh = g_down_h + ((size_t)e << 20) + (size_t)n0 * I_DIM;

    int wm = wid & 3, wn = wid >> 2;
    int m_base = wm * 32, n_base = wn * 64;

    uint32_t addrA[2];
    #pragma unroll
    for (int i = 0; i < 2; i++)
        addrA[i] = sb + DN_OFFA + (uint32_t)((m_base + i*16 + (lane & 15)) * ROWB) + ((lane >> 4) * 16);
    uint32_t addrB[4];
    #pragma unroll
    for (int jj = 0; jj < 4; jj++) {
        uint32_t row = (uint32_t)(n_base + jj*16 + (lane & 7) + (((lane >> 4) & 1) << 3));
        addrB[jj] = sb + DN_OFFB + row * ROWB + (((lane >> 3) & 1) * 16);
    }

    int lr = tid >> 2, lc = tid & 3;
    int ra0 = (lr      < mlim) ? lr      : (mlim - 1);
    int ra1 = (lr + 64 < mlim) ? lr + 64 : (mlim - 1);
    const __half* A0 = g_act + (size_t)(bse + m0 + ra0) * I_DIM;
    const __half* A1 = g_act + (size_t)(bse + m0 + ra1) * I_DIM;

    float cc[2][8][4] = {};

    #pragma unroll
    for (int s = 0; s < STAGES-1; s++) {
        int k0 = s * 32;
        uint32_t dA = sb + DN_OFFA + s * DN_STG;
        uint32_t dB = sb + DN_OFFB + s * DN_STG;
        cp16(dA + lr*ROWB        + lc*16, A0 + k0 + lc*8);
        cp16(dA + (lr+64)*ROWB   + lc*16, A1 + k0 + lc*8);
        cp16(dB + lr*ROWB        + lc*16, Dh + (size_t)lr       * I_DIM + k0 + lc*8);
        cp16(dB + (lr+64)*ROWB   + lc*16, Dh + (size_t)(lr+64)  * I_DIM + k0 + lc*8);
        CP_COMMIT();
    }

    const int NIT = I_DIM / 32;
    int cons = 0, fill = STAGES - 1;
    for (int it = 0; it < NIT; it++) {
        CP_WAIT3();
        __syncthreads();
        if (it + STAGES-1 < NIT) {
            int k0 = (it + STAGES-1) * 32;
            uint32_t dA = sb + DN_OFFA + fill * DN_STG;
            uint32_t dB = sb + DN_OFFB + fill * DN_STG;
            cp16(dA + lr*ROWB      + lc*16, A0 + k0 + lc*8);
            cp16(dA + (lr+64)*ROWB + lc*16, A1 + k0 + lc*8);
            cp16(dB + lr*ROWB      + lc*16, Dh + (size_t)lr      * I_DIM + k0 + lc*8);
            cp16(dB + (lr+64)*ROWB + lc*16, Dh + (size_t)(lr+64) * I_DIM + k0 + lc*8);
        }
        CP_COMMIT();

        uint32_t offA = (uint32_t)cons * DN_STG;
        uint32_t offB = (uint32_t)cons * DN_STG;
        #pragma unroll
        for (int ks = 0; ks < 2; ks++) {
            uint32_t a[2][4];
            #pragma unroll
            for (int i = 0; i < 2; i++) ldsm_x4(a[i], addrA[i] + offA + ks*32);
            uint32_t b[4][4];
            #pragma unroll
            for (int jj = 0; jj < 4; jj++) ldsm_x4(b[jj], addrB[jj] + offB + ks*32);
            #pragma unroll
            for (int i = 0; i < 2; i++)
                #pragma unroll
                for (int jj = 0; jj < 4; jj++) {
                    mma16816(cc[i][2*jj+0], a[i], &b[jj][0]);
                    mma16816(cc[i][2*jj+1], a[i], &b[jj][2]);
                }
        }
        if (++cons == STAGES) cons = 0;
        if (++fill == STAGES) fill = 0;
    }

    #pragma unroll
    for (int i = 0; i < 2; i++) {
        #pragma unroll
        for (int h = 0; h < 2; h++) {
            int ml = m_base + i*16 + h*8 + (lane >> 2);
            int m  = m0 + ml;
            if (m >= cnt) continue;
            float* prow = g_part + (size_t)(bse + m) * H_DIM + n0;
            #pragma unroll
            for (int j = 0; j < 8; j++) {
                int nl = n_base + j*8 + 2*(lane & 3);
                *(float2*)&prow[nl] = make_float2(cc[i][j][h*2+0], cc[i][j][h*2+1]);
            }
        }
    }
}

// ---------------------------------------------------------------------------
// 5) Combine
// ---------------------------------------------------------------------------
__global__ void combine_kernel(float* __restrict__ out) {
    int t = blockIdx.x;
    int s0 = g_slot_of[2*t], s1 = g_slot_of[2*t + 1];
    const float4* p0 = (const float4*)(g_part + (size_t)s0 * H_DIM);
    const float4* p1 = (const float4*)(g_part + (size_t)s1 * H_DIM);
    float4* o = (float4*)(out + (size_t)t * H_DIM);
    for (int i = threadIdx.x; i < H_DIM / 4; i += blockDim.x) {
        float4 a = p0[i], b = p1[i];
        o[i] = make_float4(a.x + b.x, a.y + b.y, a.z + b.z, a.w + b.w);
    }
}

// ---------------------------------------------------------------------------
extern "C" void kernel_launch(void* const* d_in, const int* in_sizes, int n_in,
                              void* d_out, int out_size) {
    const float* hidden   = (const float*)d_in[0];
    const float* router_w = (const float*)d_in[1];
    const float* gate_w   = (const float*)d_in[2];
    const float* up_w     = (const float*)d_in[3];
    const float* down_w   = (const float*)d_in[4];
    float* out = (float*)d_out;

    cudaFuncSetAttribute(gateup_mma, cudaFuncAttributeMaxDynamicSharedMemorySize, GU_SMEM);
    cudaFuncSetAttribute(down_mma,   cudaFuncAttributeMaxDynamicSharedMemorySize, DN_SMEM);
    cudaFuncSetAttribute(gateup_mma, cudaFuncAttributePreferredSharedMemoryCarveout,
                         cudaSharedmemCarveoutMaxShared);
    cudaFuncSetAttribute(down_mma,   cudaFuncAttributePreferredSharedMemoryCarveout,
                         cudaSharedmemCarveoutMaxShared);

    __half* gate_h; cudaGetSymbolAddress((void**)&gate_h, g_gate_h);
    __half* up_h;   cudaGetSymbolAddress((void**)&up_h,   g_up_h);
    __half* down_h; cudaGetSymbolAddress((void**)&down_h, g_down_h);
    __half* xh;     cudaGetSymbolAddress((void**)&xh,     g_xh);

    cvt_all_kernel<<<(N8_TOT + 255)/256, 256>>>(gate_w, up_w, down_w, hidden,
                                                gate_h, up_h, down_h, xh);

    router_kernel<<<T_TOK, 512>>>(hidden, router_w);
    build_kernel<<<1, 512>>>();

    dim3 gridG(I_DIM / 64, NPAIR / 128, E_NUM);
    gateup_mma<<<gridG, 256, GU_SMEM>>>(xh);

    dim3 gridD(H_DIM / 128, NPAIR / 128, E_NUM);
    down_mma<<<gridD, 256, DN_SMEM>>>();

    combine_kernel<<<T_TOK, 256>>>(out);
}

// round 8
// speedup vs baseline: 1.1851x; 1.1154x over previous
#include <cuda_runtime.h>
#include <cuda_fp16.h>
#include <math.h>
#include <cstdint>

// Problem constants
#define T_TOK   2048
#define H_DIM   1024
#define E_NUM   16
#define I_DIM   1024
#define NPAIR   (T_TOK*2)
#define NMT     48            // max padded 128-row m-tiles (32 + 15 + pad)
#define NPAD    (NMT*128)     // 6144 padded slots
#define WELEM   (E_NUM*I_DIM*H_DIM)

// Tiled/swizzled storage (bytes)
__device__ __align__(16) unsigned char g_gate_t[16*16*32*4096]; // [e][nt16][ks32] 4KB blocks
__device__ __align__(16) unsigned char g_up_t  [16*16*32*4096];
__device__ __align__(16) unsigned char g_down_t[16*8*32*8192];  // [e][nt8][ks32] 8KB blocks
__device__ __align__(16) unsigned char g_ax    [NMT*32*8192];   // gathered x, tiled
__device__ __align__(16) unsigned char g_act2  [NMT*32*8192];   // gateup out, tiled (down A)
__device__ float  g_part[NPAD * H_DIM];
__device__ int    g_expert_of[NPAIR];
__device__ float  g_weight_of[NPAIR];
__device__ int    g_base [E_NUM];       // padded base (multiple of 128)
__device__ int    g_count[E_NUM];
__device__ int    g_pair_token[NPAD];
__device__ float  g_pair_w   [NPAD];
__device__ int    g_slot_of  [NPAIR];

// ---------------------------------------------------------------------------
// helpers
// ---------------------------------------------------------------------------
__device__ __forceinline__ uint32_t smem_u32(const void* p) {
    uint32_t a;
    asm("{ .reg .u64 t; cvta.to.shared.u64 t, %1; cvt.u32.u64 %0, t; }" : "=r"(a) : "l"(p));
    return a;
}
__device__ __forceinline__ void ldsm_x4(uint32_t* r, uint32_t addr) {
    asm volatile("ldmatrix.sync.aligned.m8n8.x4.shared.b16 {%0,%1,%2,%3}, [%4];"
                 : "=r"(r[0]), "=r"(r[1]), "=r"(r[2]), "=r"(r[3]) : "r"(addr));
}
__device__ __forceinline__ void mma16816(float* c, const uint32_t* a, const uint32_t* b) {
    asm volatile("mma.sync.aligned.m16n8k16.row.col.f32.f16.f16.f32 "
                 "{%0,%1,%2,%3}, {%4,%5,%6,%7}, {%8,%9}, {%0,%1,%2,%3};"
                 : "+f"(c[0]), "+f"(c[1]), "+f"(c[2]), "+f"(c[3])
                 : "r"(a[0]), "r"(a[1]), "r"(a[2]), "r"(a[3]), "r"(b[0]), "r"(b[1]));
}
__device__ __forceinline__ uint32_t packh2(float x, float y) {
    __half2 h = __floats2half2_rn(x, y);
    return *(uint32_t*)&h;
}
__device__ __forceinline__ void bulk_g2s(uint32_t smem_dst, const void* gsrc,
                                         uint32_t bytes, uint32_t mbar) {
    asm volatile("cp.async.bulk.shared::cluster.global.mbarrier::complete_tx::bytes "
                 "[%0], [%1], %2, [%3];"
                 :: "r"(smem_dst), "l"(gsrc), "r"(bytes), "r"(mbar) : "memory");
}
#define MBARRIER_INIT(mbar, count) \
    asm volatile("mbarrier.init.shared.b64 [%0], %1;" \
        :: "r"((uint32_t)(mbar)), "r"((uint32_t)(count)) : "memory")
#define MBARRIER_EXPECT_TX(mbar, tx) \
    asm volatile("mbarrier.arrive.expect_tx.shared.b64 _, [%0], %1;" \
        :: "r"((uint32_t)(mbar)), "r"((uint32_t)(tx)) : "memory")
#define MBARRIER_ARRIVE(mbar) \
    asm volatile("mbarrier.arrive.shared.b64 _, [%0];" \
        :: "r"((uint32_t)(mbar)) : "memory")
#define MBARRIER_WAIT_PARITY(mbar_addr, phase_parity) do { \
    uint32_t _mbar = (uint32_t)(mbar_addr); \
    uint32_t _parity = (uint32_t)(phase_parity); \
    uint32_t _done; \
    asm volatile("{\n\t.reg .pred p;\n\t" \
        "mbarrier.try_wait.parity.acquire.cta.shared::cta.b64 p, [%1], %2;\n\t" \
        "selp.b32 %0, 1, 0, p;\n\t}" \
        : "=r"(_done) : "r"(_mbar), "r"(_parity) : "memory"); \
    if (!_done) { \
        asm volatile("{\n\t.reg .pred P1;\n\t" \
            "WAIT_LOOP_%=:\n\t" \
            "mbarrier.try_wait.parity.acquire.cta.shared::cta.b64 P1, [%0], %1, 0x989680;\n\t" \
            "@P1 bra.uni WAIT_DONE_%=;\n\t" \
            "bra.uni WAIT_LOOP_%=;\n\t" \
            "WAIT_DONE_%=:\n\t}" \
            :: "r"(_mbar), "r"(_parity) : "memory"); \
    } \
} while (0)

#define SW64K(r) (((r) & 6) << 3)   // per-row XOR key for 64B-row swizzle

// ---------------------------------------------------------------------------
// 0) cvt + retile weights into SW64-swizzled tiled blocks
// ---------------------------------------------------------------------------
#define NCH_GU (16*16*32*256)   // 2,097,152 chunks per gate/up tensor
#define NCH_DN (16*8*32*512)    // 2,097,152 chunks for down
#define NCH_TOT (2*NCH_GU + NCH_DN)

__global__ void cvt_retile_kernel(const float* __restrict__ gw,
                                  const float* __restrict__ uw,
                                  const float* __restrict__ dw) {
    int g = blockIdx.x * blockDim.x + threadIdx.x;
    if (g >= NCH_TOT) return;
    const float* src; unsigned char* dstb; size_t srcoff; uint32_t dstoff;
    if (g < 2*NCH_GU) {
        int c = (g < NCH_GU) ? g : g - NCH_GU;
        src  = (g < NCH_GU) ? gw : uw;
        dstb = (g < NCH_GU) ? g_gate_t : g_up_t;
        int b = c >> 8, w = c & 255;
        int e = b >> 9, nt = (b >> 5) & 15, ks = b & 31;
        int rloc = w >> 2, cc = w & 3;
        int row = nt*64 + rloc;
        srcoff = ((size_t)(e*1024 + row))*1024 + (ks*4 + cc)*8;
        dstoff = (uint32_t)b*4096 + ((uint32_t)(w*16) ^ SW64K(rloc));
    } else {
        int c = g - 2*NCH_GU;
        src = dw; dstb = g_down_t;
        int b = c >> 9, w = c & 511;
        int e = b >> 8, nt = (b >> 5) & 7, ks = b & 31;
        int rloc = w >> 2, cc = w & 3;
        int row = nt*128 + rloc;
        srcoff = ((size_t)(e*1024 + row))*1024 + (ks*4 + cc)*8;
        dstoff = (uint32_t)b*8192 + ((uint32_t)(w*16) ^ SW64K(rloc));
    }
    float4 a = *(const float4*)(src + srcoff);
    float4 bb = *(const float4*)(src + srcoff + 4);
    uint4 o;
    o.x = packh2(a.x, a.y);  o.y = packh2(a.z, a.w);
    o.z = packh2(bb.x, bb.y); o.w = packh2(bb.z, bb.w);
    *(uint4*)(dstb + dstoff) = o;
}

// ---------------------------------------------------------------------------
// 1) Router
// ---------------------------------------------------------------------------
__global__ void router_kernel(const float* __restrict__ x,
                              const float* __restrict__ rw) {
    int t = blockIdx.x;
    int warp = threadIdx.x >> 5, lane = threadIdx.x & 31;
    __shared__ float logits[E_NUM];
    const float* xr = x + (size_t)t * H_DIM;
    const float* wr = rw + (size_t)warp * H_DIM;
    float s = 0.f;
    #pragma unroll 4
    for (int h = lane; h < H_DIM; h += 32) s += xr[h] * wr[h];
    #pragma unroll
    for (int o = 16; o; o >>= 1) s += __shfl_xor_sync(0xffffffffu, s, o);
    if (lane == 0) logits[warp] = s;
    __syncthreads();
    if (threadIdx.x == 0) {
        float sc[E_NUM];
        #pragma unroll
        for (int e = 0; e < E_NUM; e++) sc[e] = 1.f / (1.f + expf(-logits[e]));
        int i0 = 0;
        #pragma unroll
        for (int e = 1; e < E_NUM; e++) if (sc[e] > sc[i0]) i0 = e;
        int i1 = -1;
        #pragma unroll
        for (int e = 0; e < E_NUM; e++) {
            if (e == i0) continue;
            if (i1 < 0 || sc[e] > sc[i1]) i1 = e;
        }
        float w0 = sc[i0], w1 = sc[i1];
        float inv = 1.f / (w0 + w1 + 1e-20f);
        g_expert_of[2*t]   = i0;  g_weight_of[2*t]   = w0 * inv;
        g_expert_of[2*t+1] = i1;  g_weight_of[2*t+1] = w1 * inv;
    }
}

// ---------------------------------------------------------------------------
// 2) Build expert-sorted padded pair lists
// ---------------------------------------------------------------------------
__global__ void build_kernel() {
    __shared__ unsigned char eid[NPAIR];
    __shared__ int cnt[E_NUM], pb[E_NUM];
    int tid = threadIdx.x;
    for (int p = tid; p < NPAIR; p += blockDim.x)
        eid[p] = (unsigned char)g_expert_of[p];
    for (int s = tid; s < NPAD; s += blockDim.x) {
        g_pair_token[s] = 0;
        g_pair_w[s]     = 0.f;
    }
    __syncthreads();
    if (tid < E_NUM) {
        int c = 0;
        for (int p = 0; p < NPAIR; p++) c += (eid[p] == tid);
        cnt[tid] = c;
    }
    __syncthreads();
    if (tid == 0) {
        int acc = 0;
        for (int e = 0; e < E_NUM; e++) {
            pb[e] = acc;
            acc += ((cnt[e] + 127) >> 7) << 7;   // pad to 128
        }
    }
    __syncthreads();
    int w = tid >> 5, lane = tid & 31;
    if (w < E_NUM) {
        int e = w, pos = pb[e];
        for (int p0 = 0; p0 < NPAIR; p0 += 32) {
            int p = p0 + lane;
            bool m = (eid[p] == e);
            unsigned mask = __ballot_sync(0xffffffffu, m);
            if (m) {
                int s = pos + __popc(mask & ((1u << lane) - 1u));
                g_pair_token[s] = p >> 1;
                g_pair_w[s]     = g_weight_of[p];
                g_slot_of[p]    = s;
            }
            pos += __popc(mask);
        }
    }
    if (tid < E_NUM) { g_base[tid] = pb[tid]; g_count[tid] = cnt[tid]; }
}

// ---------------------------------------------------------------------------
// 2b) Gather x into tiled/swizzled fp16 layout (padded slots -> token 0, w=0)
// ---------------------------------------------------------------------------
#define NCH_AX (NMT*32*512)   // 786,432 chunks

__global__ void gather_kernel(const float* __restrict__ x) {
    int g = blockIdx.x * blockDim.x + threadIdx.x;
    if (g >= NCH_AX) return;
    int mt = g >> 14, rem = g & 16383;
    int ks = rem >> 9, w = rem & 511;
    int rloc = w >> 2, cc = w & 3;
    int slot = (mt << 7) + rloc;
    int tok = g_pair_token[slot];
    const float* src = x + (size_t)tok * H_DIM + ks*32 + cc*8;
    float4 a = *(const float4*)src;
    float4 b = *(const float4*)(src + 4);
    uint4 o;
    o.x = packh2(a.x, a.y); o.y = packh2(a.z, a.w);
    o.z = packh2(b.x, b.y); o.w = packh2(b.z, b.w);
    *(uint4*)(g_ax + ((size_t)(mt*32 + ks) << 13)
                   + (((uint32_t)(w*16)) ^ SW64K(rloc))) = o;
}

// ---------------------------------------------------------------------------
// 3) gateup: bulk-copy mbarrier pipeline, gate+up fused -> g_act2 (tiled)
//    CTA 128M x 64N(x2) x 32K, 8 warps (4m x 2n), 4 stages.
// ---------------------------------------------------------------------------
#define STAGES 4
#define GU_TX  16384
#define GU_SMEM 66560   // 1024 hdr + 4*8192 A + 4*4096 G + 4*4096 U

__global__ __launch_bounds__(256, 2)
void gateup_mma() {
    int e  = blockIdx.z;
    int m0 = blockIdx.y * 128;
    int bx = blockIdx.x;
    int n0 = bx * 64;
    int cnt = g_count[e];
    if (m0 >= cnt) return;
    int pb = g_base[e];

    extern __shared__ char dsm[];
    uint32_t sb = smem_u32(dsm);
    __shared__ float wrow_s[128];

    int tid = threadIdx.x, lane = tid & 31, wid = tid >> 5;
    if (tid == 0) {
        #pragma unroll
        for (int s = 0; s < STAGES; s++) {
            MBARRIER_INIT(sb + s*8, 1);          // full
            MBARRIER_INIT(sb + 32 + s*8, 256);   // empty
        }
    }
    if (tid < 128) wrow_s[tid] = g_pair_w[pb + m0 + tid];
    __syncthreads();

    int mtg = (pb + m0) >> 7;
    const unsigned char* Asrc = g_ax     + (size_t)mtg * 32 * 8192;
    const unsigned char* Gsrc = g_gate_t + ((size_t)(e*16 + bx) * 32) * 4096;
    const unsigned char* Usrc = g_up_t   + ((size_t)(e*16 + bx) * 32) * 4096;

    int wm = wid & 3, wn = wid >> 2;
    int m_base = wm * 32, n_base = wn * 32;

    uint32_t relA[2];
    #pragma unroll
    for (int i = 0; i < 2; i++) {
        int r = m_base + i*16 + (lane & 15);
        relA[i] = (uint32_t)(r*64) + (((uint32_t)(lane >> 4) * 16) ^ SW64K(r));
    }
    uint32_t relB[2];
    #pragma unroll
    for (int jj = 0; jj < 2; jj++) {
        int r = n_base + jj*16 + (lane & 7) + (((lane >> 4) & 1) << 3);
        relB[jj] = (uint32_t)(r*64) + ((((uint32_t)(lane >> 3) & 1) * 16) ^ SW64K(r));
    }

    float cg[2][4][4] = {}, cu[2][4][4] = {};

    if (tid == 0) {
        #pragma unroll
        for (int s = 0; s < STAGES-1; s++) {
            uint32_t fb = sb + s*8;
            MBARRIER_EXPECT_TX(fb, GU_TX);
            bulk_g2s(sb + 1024  + s*8192, Asrc + (size_t)s*8192, 8192, fb);
            bulk_g2s(sb + 33792 + s*4096, Gsrc + (size_t)s*4096, 4096, fb);
            bulk_g2s(sb + 50176 + s*4096, Usrc + (size_t)s*4096, 4096, fb);
        }
    }

    const int NIT = H_DIM / 32;
    for (int it = 0; it < NIT; it++) {
        if (tid == 0 && it + STAGES-1 < NIT) {
            int j = it + STAGES-1, s = j & 3;
            if (j >= STAGES) MBARRIER_WAIT_PARITY(sb + 32 + s*8, ((j >> 2) - 1) & 1);
            uint32_t fb = sb + s*8;
            MBARRIER_EXPECT_TX(fb, GU_TX);
            bulk_g2s(sb + 1024  + s*8192, Asrc + (size_t)j*8192, 8192, fb);
            bulk_g2s(sb + 33792 + s*4096, Gsrc + (size_t)j*4096, 4096, fb);
            bulk_g2s(sb + 50176 + s*4096, Usrc + (size_t)j*4096, 4096, fb);
        }
        int cs = it & 3;
        MBARRIER_WAIT_PARITY(sb + cs*8, (it >> 2) & 1);
        uint32_t bA = sb + 1024 + cs*8192;
        uint32_t bG = sb + 33792 + cs*4096;
        uint32_t bU = sb + 50176 + cs*4096;
        #pragma unroll
        for (int ks = 0; ks < 2; ks++) {
            uint32_t kk = (uint32_t)ks << 5;
            uint32_t a[2][4];
            #pragma unroll
            for (int i = 0; i < 2; i++) ldsm_x4(a[i], bA + (relA[i] ^ kk));
            uint32_t bg[2][4], bu[2][4];
            #pragma unroll
            for (int jj = 0; jj < 2; jj++) {
                ldsm_x4(bg[jj], bG + (relB[jj] ^ kk));
                ldsm_x4(bu[jj], bU + (relB[jj] ^ kk));
            }
            #pragma unroll
            for (int i = 0; i < 2; i++)
                #pragma unroll
                for (int jj = 0; jj < 2; jj++) {
                    mma16816(cg[i][2*jj+0], a[i], &bg[jj][0]);
                    mma16816(cg[i][2*jj+1], a[i], &bg[jj][2]);
                    mma16816(cu[i][2*jj+0], a[i], &bu[jj][0]);
                    mma16816(cu[i][2*jj+1], a[i], &bu[jj][2]);
                }
        }
        MBARRIER_ARRIVE(sb + 32 + cs*8);
    }

    // epilogue: write w*silu(g)*u directly into down's tiled layout
    int ks2 = (n0 >> 5) + wn;
    unsigned char* actb = g_act2 + ((size_t)(mtg*32 + ks2)) * 8192;
    uint32_t toff = (uint32_t)(lane & 3) * 4;
    #pragma unroll
    for (int i = 0; i < 2; i++) {
        #pragma unroll
        for (int h = 0; h < 2; h++) {
            int ml = m_base + i*16 + h*8 + (lane >> 2);
            int m  = m0 + ml;
            if (m >= cnt) continue;
            float w = wrow_s[ml];
            uint32_t rbase = (uint32_t)(ml*64);
            uint32_t kr = SW64K(ml);
            #pragma unroll
            for (int j = 0; j < 4; j++) {
                float g0 = cg[i][j][h*2+0], g1 = cg[i][j][h*2+1];
                float u0 = cu[i][j][h*2+0], u1 = cu[i][j][h*2+1];
                float a0 = w * (g0 / (1.f + __expf(-g0))) * u0;
                float a1 = w * (g1 / (1.f + __expf(-g1))) * u1;
                uint32_t off = rbase + (((uint32_t)(j*16)) ^ kr) + toff;
                *(uint32_t*)(actb + off) = packh2(a0, a1);
            }
        }
    }
}

// ---------------------------------------------------------------------------
// 4) down: bulk-copy mbarrier pipeline -> g_part
//    CTA 128M x 128N x 32K, 8 warps (4m x 2n), 4 stages.
// ---------------------------------------------------------------------------
#define DN_TX  16384
#define DN_SMEM 66560  // 1024 hdr + 4*8192 A + 4*8192 B

__global__ __launch_bounds__(256, 2)
void down_mma() {
    int e  = blockIdx.z;
    int m0 = blockIdx.y * 128;
    int bx = blockIdx.x;
    int n0 = bx * 128;
    int cnt = g_count[e];
    if (m0 >= cnt) return;
    int pb = g_base[e];

    extern __shared__ char dsm[];
    uint32_t sb = smem_u32(dsm);

    int tid = threadIdx.x, lane = tid & 31, wid = tid >> 5;
    if (tid == 0) {
        #pragma unroll
        for (int s = 0; s < STAGES; s++) {
            MBARRIER_INIT(sb + s*8, 1);
            MBARRIER_INIT(sb + 32 + s*8, 256);
        }
    }
    __syncthreads();

    int mtg = (pb + m0) >> 7;
    const unsigned char* Asrc = g_act2  + (size_t)mtg * 32 * 8192;
    const unsigned char* Bsrc = g_down_t + ((size_t)(e*8 + bx) * 32) * 8192;

    int wm = wid & 3, wn = wid >> 2;
    int m_base = wm * 32, n_base = wn * 64;

    uint32_t relA[2];
    #pragma unroll
    for (int i = 0; i < 2; i++) {
        int r = m_base + i*16 + (lane & 15);
        relA[i] = (uint32_t)(r*64) + (((uint32_t)(lane >> 4) * 16) ^ SW64K(r));
    }
    uint32_t relB[4];
    #pragma unroll
    for (int jj = 0; jj < 4; jj++) {
        int r = n_base + jj*16 + (lane & 7) + (((lane >> 4) & 1) << 3);
        relB[jj] = (uint32_t)(r*64) + ((((uint32_t)(lane >> 3) & 1) * 16) ^ SW64K(r));
    }

    float cc[2][8][4] = {};

    if (tid == 0) {
        #pragma unroll
        for (int s = 0; s < STAGES-1; s++) {
            uint32_t fb = sb + s*8;
            MBARRIER_EXPECT_TX(fb, DN_TX);
            bulk_g2s(sb + 1024  + s*8192, Asrc + (size_t)s*8192, 8192, fb);
            bulk_g2s(sb + 33792 + s*8192, Bsrc + (size_t)s*8192, 8192, fb);
        }
    }

    const int NIT = I_DIM / 32;
    for (int it = 0; it < NIT; it++) {
        if (tid == 0 && it + STAGES-1 < NIT) {
            int j = it + STAGES-1, s = j & 3;
            if (j >= STAGES) MBARRIER_WAIT_PARITY(sb + 32 + s*8, ((j >> 2) - 1) & 1);
            uint32_t fb = sb + s*8;
            MBARRIER_EXPECT_TX(fb, DN_TX);
            bulk_g2s(sb + 1024  + s*8192, Asrc + (size_t)j*8192, 8192, fb);
            bulk_g2s(sb + 33792 + s*8192, Bsrc + (size_t)j*8192, 8192, fb);
        }
        int cs = it & 3;
        MBARRIER_WAIT_PARITY(sb + cs*8, (it >> 2) & 1);
        uint32_t bA = sb + 1024 + cs*8192;
        uint32_t bB = sb + 33792 + cs*8192;
        #pragma unroll
        for (int ks = 0; ks < 2; ks++) {
            uint32_t kk = (uint32_t)ks << 5;
            uint32_t a[2][4];
            #pragma unroll
            for (int i = 0; i < 2; i++) ldsm_x4(a[i], bA + (relA[i] ^ kk));
            uint32_t b[4][4];
            #pragma unroll
            for (int jj = 0; jj < 4; jj++) ldsm_x4(b[jj], bB + (relB[jj] ^ kk));
            #pragma unroll
            for (int i = 0; i < 2; i++)
                #pragma unroll
                for (int jj = 0; jj < 4; jj++) {
                    mma16816(cc[i][2*jj+0], a[i], &b[jj][0]);
                    mma16816(cc[i][2*jj+1], a[i], &b[jj][2]);
                }
        }
        MBARRIER_ARRIVE(sb + 32 + cs*8);
    }

    #pragma unroll
    for (int i = 0; i < 2; i++) {
        #pragma unroll
        for (int h = 0; h < 2; h++) {
            int ml = m_base + i*16 + h*8 + (lane >> 2);
            int m  = m0 + ml;
            if (m >= cnt) continue;
            float* prow = g_part + (size_t)(pb + m0 + ml) * H_DIM + n0;
            #pragma unroll
            for (int j = 0; j < 8; j++) {
                int nl = n_base + j*8 + 2*(lane & 3);
                *(float2*)&prow[nl] = make_float2(cc[i][j][h*2+0], cc[i][j][h*2+1]);
            }
        }
    }
}

// ---------------------------------------------------------------------------
// 5) Combine
// ---------------------------------------------------------------------------
__global__ void combine_kernel(float* __restrict__ out) {
    int t = blockIdx.x;
    int s0 = g_slot_of[2*t], s1 = g_slot_of[2*t + 1];
    const float4* p0 = (const float4*)(g_part + (size_t)s0 * H_DIM);
    const float4* p1 = (const float4*)(g_part + (size_t)s1 * H_DIM);
    float4* o = (float4*)(out + (size_t)t * H_DIM);
    for (int i = threadIdx.x; i < H_DIM / 4; i += blockDim.x) {
        float4 a = p0[i], b = p1[i];
        o[i] = make_float4(a.x + b.x, a.y + b.y, a.z + b.z, a.w + b.w);
    }
}

// ---------------------------------------------------------------------------
extern "C" void kernel_launch(void* const* d_in, const int* in_sizes, int n_in,
                              void* d_out, int out_size) {
    const float* hidden   = (const float*)d_in[0];
    const float* router_w = (const float*)d_in[1];
    const float* gate_w   = (const float*)d_in[2];
    const float* up_w     = (const float*)d_in[3];
    const float* down_w   = (const float*)d_in[4];
    float* out = (float*)d_out;

    cudaFuncSetAttribute(gateup_mma, cudaFuncAttributeMaxDynamicSharedMemorySize, GU_SMEM);
    cudaFuncSetAttribute(down_mma,   cudaFuncAttributeMaxDynamicSharedMemorySize, DN_SMEM);
    cudaFuncSetAttribute(gateup_mma, cudaFuncAttributePreferredSharedMemoryCarveout,
                         cudaSharedmemCarveoutMaxShared);
    cudaFuncSetAttribute(down_mma,   cudaFuncAttributePreferredSharedMemoryCarveout,
                         cudaSharedmemCarveoutMaxShared);

    cvt_retile_kernel<<<(NCH_TOT + 255)/256, 256>>>(gate_w, up_w, down_w);

    router_kernel<<<T_TOK, 512>>>(hidden, router_w);
    build_kernel<<<1, 512>>>();
    gather_kernel<<<(NCH_AX + 255)/256, 256>>>(hidden);

    dim3 gridG(16, 32, E_NUM);
    gateup_mma<<<gridG, 256, GU_SMEM>>>();

    dim3 gridD(8, 32, E_NUM);
    down_mma<<<gridD, 256, DN_SMEM>>>();

    combine_kernel<<<T_TOK, 256>>>(out);
}

// round 9
// speedup vs baseline: 1.1908x; 1.0048x over previous
#include <cuda_runtime.h>
#include <cuda_fp16.h>
#include <math.h>
#include <cstdint>

// Problem constants
#define T_TOK   2048
#define H_DIM   1024
#define E_NUM   16
#define I_DIM   1024
#define NPAIR   (T_TOK*2)
#define NMT     48            // max padded 128-row m-tiles
#define NPAD    (NMT*128)
#define WELEM   (E_NUM*I_DIM*H_DIM)

// Tiled/swizzled storage (bytes)
__device__ __align__(16) unsigned char g_gate_t[16*16*32*4096];
__device__ __align__(16) unsigned char g_up_t  [16*16*32*4096];
__device__ __align__(16) unsigned char g_down_t[16*8*32*8192];
__device__ __align__(16) unsigned char g_ax    [NMT*32*8192];
__device__ __align__(16) unsigned char g_act2  [NMT*32*8192];
__device__ float  g_part[NPAD * H_DIM];
__device__ int    g_expert_of[NPAIR];
__device__ float  g_weight_of[NPAIR];
__device__ int    g_base [E_NUM];
__device__ int    g_count[E_NUM];
__device__ int    g_pair_token[NPAD];
__device__ float  g_pair_w   [NPAD];
__device__ int    g_slot_of  [NPAIR];

// ---------------------------------------------------------------------------
// helpers
// ---------------------------------------------------------------------------
__device__ __forceinline__ uint32_t smem_u32(const void* p) {
    uint32_t a;
    asm("{ .reg .u64 t; cvta.to.shared.u64 t, %1; cvt.u32.u64 %0, t; }" : "=r"(a) : "l"(p));
    return a;
}
__device__ __forceinline__ void ldsm_x4(uint32_t* r, uint32_t addr) {
    asm volatile("ldmatrix.sync.aligned.m8n8.x4.shared.b16 {%0,%1,%2,%3}, [%4];"
                 : "=r"(r[0]), "=r"(r[1]), "=r"(r[2]), "=r"(r[3]) : "r"(addr));
}
__device__ __forceinline__ void mma16816(float* c, const uint32_t* a, const uint32_t* b) {
    asm volatile("mma.sync.aligned.m16n8k16.row.col.f32.f16.f16.f32 "
                 "{%0,%1,%2,%3}, {%4,%5,%6,%7}, {%8,%9}, {%0,%1,%2,%3};"
                 : "+f"(c[0]), "+f"(c[1]), "+f"(c[2]), "+f"(c[3])
                 : "r"(a[0]), "r"(a[1]), "r"(a[2]), "r"(a[3]), "r"(b[0]), "r"(b[1]));
}
__device__ __forceinline__ uint32_t packh2(float x, float y) {
    __half2 h = __floats2half2_rn(x, y);
    return *(uint32_t*)&h;
}
__device__ __forceinline__ void bulk_g2s(uint32_t smem_dst, const void* gsrc,
                                         uint32_t bytes, uint32_t mbar) {
    asm volatile("cp.async.bulk.shared::cluster.global.mbarrier::complete_tx::bytes "
                 "[%0], [%1], %2, [%3];"
                 :: "r"(smem_dst), "l"(gsrc), "r"(bytes), "r"(mbar) : "memory");
}
#define MBARRIER_INIT(mbar, count) \
    asm volatile("mbarrier.init.shared.b64 [%0], %1;" \
        :: "r"((uint32_t)(mbar)), "r"((uint32_t)(count)) : "memory")
#define MBARRIER_EXPECT_TX(mbar, tx) \
    asm volatile("mbarrier.arrive.expect_tx.shared.b64 _, [%0], %1;" \
        :: "r"((uint32_t)(mbar)), "r"((uint32_t)(tx)) : "memory")
#define MBARRIER_ARRIVE(mbar) \
    asm volatile("mbarrier.arrive.shared.b64 _, [%0];" \
        :: "r"((uint32_t)(mbar)) : "memory")
#define MBARRIER_WAIT_PARITY(mbar_addr, phase_parity) do { \
    uint32_t _mbar = (uint32_t)(mbar_addr); \
    uint32_t _parity = (uint32_t)(phase_parity); \
    uint32_t _done; \
    asm volatile("{\n\t.reg .pred p;\n\t" \
        "mbarrier.try_wait.parity.acquire.cta.shared::cta.b64 p, [%1], %2;\n\t" \
        "selp.b32 %0, 1, 0, p;\n\t}" \
        : "=r"(_done) : "r"(_mbar), "r"(_parity) : "memory"); \
    if (!_done) { \
        asm volatile("{\n\t.reg .pred P1;\n\t" \
            "WAIT_LOOP_%=:\n\t" \
            "mbarrier.try_wait.parity.acquire.cta.shared::cta.b64 P1, [%0], %1, 0x989680;\n\t" \
            "@P1 bra.uni WAIT_DONE_%=;\n\t" \
            "bra.uni WAIT_LOOP_%=;\n\t" \
            "WAIT_DONE_%=:\n\t}" \
            :: "r"(_mbar), "r"(_parity) : "memory"); \
    } \
} while (0)

#define SW64K(r) (((r) & 6) << 3)

// ---------------------------------------------------------------------------
// 0) gate/up cvt + retile, with router fused into blocks [0, T_TOK)
// ---------------------------------------------------------------------------
#define NCH_GU  (16*16*32*256)      // per tensor
#define NCH_GU2 (2*NCH_GU)          // 4,194,304 -> 16384 blocks x 256

__global__ void cvt_gu_router_kernel(const float* __restrict__ gw,
                                     const float* __restrict__ uw,
                                     const float* __restrict__ x,
                                     const float* __restrict__ rw) {
    int tid = threadIdx.x;
    int g = blockIdx.x * 256 + tid;
    {
        int c = (g < NCH_GU) ? g : g - NCH_GU;
        const float* src = (g < NCH_GU) ? gw : uw;
        unsigned char* dstb = (g < NCH_GU) ? g_gate_t : g_up_t;
        int b = c >> 8, w = c & 255;
        int e = b >> 9, nt = (b >> 5) & 15, ks = b & 31;
        int rloc = w >> 2, cc = w & 3;
        int row = nt*64 + rloc;
        size_t srcoff = ((size_t)(e*1024 + row))*1024 + (ks*4 + cc)*8;
        uint32_t dstoff = (uint32_t)b*4096 + ((uint32_t)(w*16) ^ SW64K(rloc));
        float4 a = *(const float4*)(src + srcoff);
        float4 bb = *(const float4*)(src + srcoff + 4);
        uint4 o;
        o.x = packh2(a.x, a.y);  o.y = packh2(a.z, a.w);
        o.z = packh2(bb.x, bb.y); o.w = packh2(bb.z, bb.w);
        *(uint4*)(dstb + dstoff) = o;
    }

    // router: blocks [0, T_TOK) also route token t = blockIdx.x
    if (blockIdx.x < T_TOK) {
        int t = blockIdx.x;
        int warp = tid >> 5, lane = tid & 31;
        __shared__ float logits[E_NUM];
        const float* xr = x + (size_t)t * H_DIM;
        const float* w0p = rw + (size_t)(2*warp)     * H_DIM;
        const float* w1p = rw + (size_t)(2*warp + 1) * H_DIM;
        float s0 = 0.f, s1 = 0.f;
        #pragma unroll 4
        for (int h = lane; h < H_DIM; h += 32) {
            float xv = xr[h];
            s0 += xv * w0p[h];
            s1 += xv * w1p[h];
        }
        #pragma unroll
        for (int o = 16; o; o >>= 1) {
            s0 += __shfl_xor_sync(0xffffffffu, s0, o);
            s1 += __shfl_xor_sync(0xffffffffu, s1, o);
        }
        if (lane == 0) { logits[2*warp] = s0; logits[2*warp + 1] = s1; }
        __syncthreads();
        if (tid == 0) {
            float sc[E_NUM];
            #pragma unroll
            for (int e = 0; e < E_NUM; e++) sc[e] = 1.f / (1.f + expf(-logits[e]));
            int i0 = 0;
            #pragma unroll
            for (int e = 1; e < E_NUM; e++) if (sc[e] > sc[i0]) i0 = e;
            int i1 = -1;
            #pragma unroll
            for (int e = 0; e < E_NUM; e++) {
                if (e == i0) continue;
                if (i1 < 0 || sc[e] > sc[i1]) i1 = e;
            }
            float w0 = sc[i0], w1 = sc[i1];
            float inv = 1.f / (w0 + w1 + 1e-20f);
            g_expert_of[2*t]   = i0;  g_weight_of[2*t]   = w0 * inv;
            g_expert_of[2*t+1] = i1;  g_weight_of[2*t+1] = w1 * inv;
        }
    }
}

// ---------------------------------------------------------------------------
// 2) Build expert-sorted padded pair lists
// ---------------------------------------------------------------------------
__global__ void build_kernel() {
    __shared__ unsigned char eid[NPAIR];
    __shared__ int cnt[E_NUM], pb[E_NUM];
    int tid = threadIdx.x;
    for (int p = tid; p < NPAIR; p += blockDim.x)
        eid[p] = (unsigned char)g_expert_of[p];
    for (int s = tid; s < NPAD; s += blockDim.x) {
        g_pair_token[s] = 0;
        g_pair_w[s]     = 0.f;
    }
    __syncthreads();
    if (tid < E_NUM) {
        int c = 0;
        for (int p = 0; p < NPAIR; p++) c += (eid[p] == tid);
        cnt[tid] = c;
    }
    __syncthreads();
    if (tid == 0) {
        int acc = 0;
        for (int e = 0; e < E_NUM; e++) {
            pb[e] = acc;
            acc += ((cnt[e] + 127) >> 7) << 7;
        }
    }
    __syncthreads();
    int w = tid >> 5, lane = tid & 31;
    if (w < E_NUM) {
        int e = w, pos = pb[e];
        for (int p0 = 0; p0 < NPAIR; p0 += 32) {
            int p = p0 + lane;
            bool m = (eid[p] == e);
            unsigned mask = __ballot_sync(0xffffffffu, m);
            if (m) {
                int s = pos + __popc(mask & ((1u << lane) - 1u));
                g_pair_token[s] = p >> 1;
                g_pair_w[s]     = g_weight_of[p];
                g_slot_of[p]    = s;
            }
            pos += __popc(mask);
        }
    }
    if (tid < E_NUM) { g_base[tid] = pb[tid]; g_count[tid] = cnt[tid]; }
}

// ---------------------------------------------------------------------------
// 2b) Gather x into tiled/swizzled fp16 layout
// ---------------------------------------------------------------------------
#define NCH_AX (NMT*32*512)

__global__ void gather_kernel(const float* __restrict__ x) {
    int g = blockIdx.x * blockDim.x + threadIdx.x;
    if (g >= NCH_AX) return;
    int mt = g >> 14, rem = g & 16383;
    int ks = rem >> 9, w = rem & 511;
    int rloc = w >> 2, cc = w & 3;
    int slot = (mt << 7) + rloc;
    int tok = g_pair_token[slot];
    const float* src = x + (size_t)tok * H_DIM + ks*32 + cc*8;
    float4 a = *(const float4*)src;
    float4 b = *(const float4*)(src + 4);
    uint4 o;
    o.x = packh2(a.x, a.y); o.y = packh2(a.z, a.w);
    o.z = packh2(b.x, b.y); o.w = packh2(b.z, b.w);
    *(uint4*)(g_ax + ((size_t)(mt*32 + ks) << 13)
                   + (((uint32_t)(w*16)) ^ SW64K(rloc))) = o;
}

// ---------------------------------------------------------------------------
// 3) gateup: bulk-copy mbarrier pipeline + fused down-weight cvt preamble
// ---------------------------------------------------------------------------
#define STAGES 4
#define GU_TX  16384
#define GU_SMEM 66560

__global__ __launch_bounds__(256, 2)
void gateup_mma(const float* __restrict__ dw) {
    int tid = threadIdx.x, lane = tid & 31, wid = tid >> 5;

    // --- fused down-weight cvt: one 16B chunk per thread, all 8192 CTAs ---
    {
        int flat = blockIdx.x + blockIdx.y * 16 + blockIdx.z * 512;
        int c = flat * 256 + tid;          // [0, 2,097,152) == NCH_DN
        int b = c >> 9, w = c & 511;
        int e = b >> 8, nt = (b >> 5) & 7, ks = b & 31;
        int rloc = w >> 2, cc = w & 3;
        int row = nt*128 + rloc;
        size_t srcoff = ((size_t)(e*1024 + row))*1024 + (ks*4 + cc)*8;
        float4 a = *(const float4*)(dw + srcoff);
        float4 bb = *(const float4*)(dw + srcoff + 4);
        uint4 o;
        o.x = packh2(a.x, a.y);  o.y = packh2(a.z, a.w);
        o.z = packh2(bb.x, bb.y); o.w = packh2(bb.z, bb.w);
        *(uint4*)(g_down_t + (uint32_t)b*8192 + ((uint32_t)(w*16) ^ SW64K(rloc))) = o;
    }

    int e  = blockIdx.z;
    int m0 = blockIdx.y * 128;
    int bx = blockIdx.x;
    int n0 = bx * 64;
    int cnt = g_count[e];
    if (m0 >= cnt) return;
    int pb = g_base[e];

    extern __shared__ char dsm[];
    uint32_t sb = smem_u32(dsm);
    __shared__ float wrow_s[128];

    if (tid == 0) {
        #pragma unroll
        for (int s = 0; s < STAGES; s++) {
            MBARRIER_INIT(sb + s*8, 1);          // full
            MBARRIER_INIT(sb + 32 + s*8, 8);     // empty: one arrive per warp
        }
    }
    if (tid < 128) wrow_s[tid] = g_pair_w[pb + m0 + tid];
    __syncthreads();

    int mtg = (pb + m0) >> 7;
    const unsigned char* Asrc = g_ax     + (size_t)mtg * 32 * 8192;
    const unsigned char* Gsrc = g_gate_t + ((size_t)(e*16 + bx) * 32) * 4096;
    const unsigned char* Usrc = g_up_t   + ((size_t)(e*16 + bx) * 32) * 4096;

    int wm = wid & 3, wn = wid >> 2;
    int m_base = wm * 32, n_base = wn * 32;

    uint32_t relA[2];
    #pragma unroll
    for (int i = 0; i < 2; i++) {
        int r = m_base + i*16 + (lane & 15);
        relA[i] = (uint32_t)(r*64) + (((uint32_t)(lane >> 4) * 16) ^ SW64K(r));
    }
    uint32_t relB[2];
    #pragma unroll
    for (int jj = 0; jj < 2; jj++) {
        int r = n_base + jj*16 + (lane & 7) + (((lane >> 4) & 1) << 3);
        relB[jj] = (uint32_t)(r*64) + ((((uint32_t)(lane >> 3) & 1) * 16) ^ SW64K(r));
    }

    float cg[2][4][4] = {}, cu[2][4][4] = {};

    if (tid == 0) {
        #pragma unroll
        for (int s = 0; s < STAGES-1; s++) {
            uint32_t fb = sb + s*8;
            MBARRIER_EXPECT_TX(fb, GU_TX);
            bulk_g2s(sb + 1024  + s*8192, Asrc + (size_t)s*8192, 8192, fb);
            bulk_g2s(sb + 33792 + s*4096, Gsrc + (size_t)s*4096, 4096, fb);
            bulk_g2s(sb + 50176 + s*4096, Usrc + (size_t)s*4096, 4096, fb);
        }
    }

    const int NIT = H_DIM / 32;
    for (int it = 0; it < NIT; it++) {
        if (tid == 0 && it + STAGES-1 < NIT) {
            int j = it + STAGES-1, s = j & 3;
            if (j >= STAGES) MBARRIER_WAIT_PARITY(sb + 32 + s*8, ((j >> 2) - 1) & 1);
            uint32_t fb = sb + s*8;
            MBARRIER_EXPECT_TX(fb, GU_TX);
            bulk_g2s(sb + 1024  + s*8192, Asrc + (size_t)j*8192, 8192, fb);
            bulk_g2s(sb + 33792 + s*4096, Gsrc + (size_t)j*4096, 4096, fb);
            bulk_g2s(sb + 50176 + s*4096, Usrc + (size_t)j*4096, 4096, fb);
        }
        int cs = it & 3;
        MBARRIER_WAIT_PARITY(sb + cs*8, (it >> 2) & 1);
        uint32_t bA = sb + 1024 + cs*8192;
        uint32_t bG = sb + 33792 + cs*4096;
        uint32_t bU = sb + 50176 + cs*4096;
        #pragma unroll
        for (int ks = 0; ks < 2; ks++) {
            uint32_t kk = (uint32_t)ks << 5;
            uint32_t a[2][4];
            #pragma unroll
            for (int i = 0; i < 2; i++) ldsm_x4(a[i], bA + (relA[i] ^ kk));
            uint32_t bg[2][4], bu[2][4];
            #pragma unroll
            for (int jj = 0; jj < 2; jj++) {
                ldsm_x4(bg[jj], bG + (relB[jj] ^ kk));
                ldsm_x4(bu[jj], bU + (relB[jj] ^ kk));
            }
            #pragma unroll
            for (int i = 0; i < 2; i++)
                #pragma unroll
                for (int jj = 0; jj < 2; jj++) {
                    mma16816(cg[i][2*jj+0], a[i], &bg[jj][0]);
                    mma16816(cg[i][2*jj+1], a[i], &bg[jj][2]);
                    mma16816(cu[i][2*jj+0], a[i], &bu[jj][0]);
                    mma16816(cu[i][2*jj+1], a[i], &bu[jj][2]);
                }
        }
        if (lane == 0) MBARRIER_ARRIVE(sb + 32 + cs*8);
    }

    // epilogue: write w*silu(g)*u directly into down's tiled layout
    int ks2 = (n0 >> 5) + wn;
    unsigned char* actb = g_act2 + ((size_t)(mtg*32 + ks2)) * 8192;
    uint32_t toff = (uint32_t)(lane & 3) * 4;
    #pragma unroll
    for (int i = 0; i < 2; i++) {
        #pragma unroll
        for (int h = 0; h < 2; h++) {
            int ml = m_base + i*16 + h*8 + (lane >> 2);
            int m  = m0 + ml;
            if (m >= cnt) continue;
            float w = wrow_s[ml];
            uint32_t rbase = (uint32_t)(ml*64);
            uint32_t kr = SW64K(ml);
            #pragma unroll
            for (int j = 0; j < 4; j++) {
                float g0 = cg[i][j][h*2+0], g1 = cg[i][j][h*2+1];
                float u0 = cu[i][j][h*2+0], u1 = cu[i][j][h*2+1];
                float a0 = w * (g0 / (1.f + __expf(-g0))) * u0;
                float a1 = w * (g1 / (1.f + __expf(-g1))) * u1;
                uint32_t off = rbase + (((uint32_t)(j*16)) ^ kr) + toff;
                *(uint32_t*)(actb + off) = packh2(a0, a1);
            }
        }
    }
}

// ---------------------------------------------------------------------------
// 4) down: bulk-copy mbarrier pipeline -> g_part
// ---------------------------------------------------------------------------
#define DN_TX  16384
#define DN_SMEM 66560

__global__ __launch_bounds__(256, 2)
void down_mma() {
    int e  = blockIdx.z;
    int m0 = blockIdx.y * 128;
    int bx = blockIdx.x;
    int n0 = bx * 128;
    int cnt = g_count[e];
    if (m0 >= cnt) return;
    int pb = g_base[e];

    extern __shared__ char dsm[];
    uint32_t sb = smem_u32(dsm);

    int tid = threadIdx.x, lane = tid & 31, wid = tid >> 5;
    if (tid == 0) {
        #pragma unroll
        for (int s = 0; s < STAGES; s++) {
            MBARRIER_INIT(sb + s*8, 1);
            MBARRIER_INIT(sb + 32 + s*8, 8);
        }
    }
    __syncthreads();

    int mtg = (pb + m0) >> 7;
    const unsigned char* Asrc = g_act2  + (size_t)mtg * 32 * 8192;
    const unsigned char* Bsrc = g_down_t + ((size_t)(e*8 + bx) * 32) * 8192;

    int wm = wid & 3, wn = wid >> 2;
    int m_base = wm * 32, n_base = wn * 64;

    uint32_t relA[2];
    #pragma unroll
    for (int i = 0; i < 2; i++) {
        int r = m_base + i*16 + (lane & 15);
        relA[i] = (uint32_t)(r*64) + (((uint32_t)(lane >> 4) * 16) ^ SW64K(r));
    }
    uint32_t relB[4];
    #pragma unroll
    for (int jj = 0; jj < 4; jj++) {
        int r = n_base + jj*16 + (lane & 7) + (((lane >> 4) & 1) << 3);
        relB[jj] = (uint32_t)(r*64) + ((((uint32_t)(lane >> 3) & 1) * 16) ^ SW64K(r));
    }

    float cc[2][8][4] = {};

    if (tid == 0) {
        #pragma unroll
        for (int s = 0; s < STAGES-1; s++) {
            uint32_t fb = sb + s*8;
            MBARRIER_EXPECT_TX(fb, DN_TX);
            bulk_g2s(sb + 1024  + s*8192, Asrc + (size_t)s*8192, 8192, fb);
            bulk_g2s(sb + 33792 + s*8192, Bsrc + (size_t)s*8192, 8192, fb);
        }
    }

    const int NIT = I_DIM / 32;
    for (int it = 0; it < NIT; it++) {
        if (tid == 0 && it + STAGES-1 < NIT) {
            int j = it + STAGES-1, s = j & 3;
            if (j >= STAGES) MBARRIER_WAIT_PARITY(sb + 32 + s*8, ((j >> 2) - 1) & 1);
            uint32_t fb = sb + s*8;
            MBARRIER_EXPECT_TX(fb, DN_TX);
            bulk_g2s(sb + 1024  + s*8192, Asrc + (size_t)j*8192, 8192, fb);
            bulk_g2s(sb + 33792 + s*8192, Bsrc + (size_t)j*8192, 8192, fb);
        }
        int cs = it & 3;
        MBARRIER_WAIT_PARITY(sb + cs*8, (it >> 2) & 1);
        uint32_t bA = sb + 1024 + cs*8192;
        uint32_t bB = sb + 33792 + cs*8192;
        #pragma unroll
        for (int ks = 0; ks < 2; ks++) {
            uint32_t kk = (uint32_t)ks << 5;
            uint32_t a[2][4];
            #pragma unroll
            for (int i = 0; i < 2; i++) ldsm_x4(a[i], bA + (relA[i] ^ kk));
            uint32_t b[4][4];
            #pragma unroll
            for (int jj = 0; jj < 4; jj++) ldsm_x4(b[jj], bB + (relB[jj] ^ kk));
            #pragma unroll
            for (int i = 0; i < 2; i++)
                #pragma unroll
                for (int jj = 0; jj < 4; jj++) {
                    mma16816(cc[i][2*jj+0], a[i], &b[jj][0]);
                    mma16816(cc[i][2*jj+1], a[i], &b[jj][2]);
                }
        }
        if (lane == 0) MBARRIER_ARRIVE(sb + 32 + cs*8);
    }

    #pragma unroll
    for (int i = 0; i < 2; i++) {
        #pragma unroll
        for (int h = 0; h < 2; h++) {
            int ml = m_base + i*16 + h*8 + (lane >> 2);
            int m  = m0 + ml;
            if (m >= cnt) continue;
            float* prow = g_part + (size_t)(pb + m0 + ml) * H_DIM + n0;
            #pragma unroll
            for (int j = 0; j < 8; j++) {
                int nl = n_base + j*8 + 2*(lane & 3);
                *(float2*)&prow[nl] = make_float2(cc[i][j][h*2+0], cc[i][j][h*2+1]);
            }
        }
    }
}

// ---------------------------------------------------------------------------
// 5) Combine
// ---------------------------------------------------------------------------
__global__ void combine_kernel(float* __restrict__ out) {
    int t = blockIdx.x;
    int s0 = g_slot_of[2*t], s1 = g_slot_of[2*t + 1];
    const float4* p0 = (const float4*)(g_part + (size_t)s0 * H_DIM);
    const float4* p1 = (const float4*)(g_part + (size_t)s1 * H_DIM);
    float4* o = (float4*)(out + (size_t)t * H_DIM);
    for (int i = threadIdx.x; i < H_DIM / 4; i += blockDim.x) {
        float4 a = p0[i], b = p1[i];
        o[i] = make_float4(a.x + b.x, a.y + b.y, a.z + b.z, a.w + b.w);
    }
}

// ---------------------------------------------------------------------------
extern "C" void kernel_launch(void* const* d_in, const int* in_sizes, int n_in,
                              void* d_out, int out_size) {
    const float* hidden   = (const float*)d_in[0];
    const float* router_w = (const float*)d_in[1];
    const float* gate_w   = (const float*)d_in[2];
    const float* up_w     = (const float*)d_in[3];
    const float* down_w   = (const float*)d_in[4];
    float* out = (float*)d_out;

    cudaFuncSetAttribute(gateup_mma, cudaFuncAttributeMaxDynamicSharedMemorySize, GU_SMEM);
    cudaFuncSetAttribute(down_mma,   cudaFuncAttributeMaxDynamicSharedMemorySize, DN_SMEM);
    cudaFuncSetAttribute(gateup_mma, cudaFuncAttributePreferredSharedMemoryCarveout,
                         cudaSharedmemCarveoutMaxShared);
    cudaFuncSetAttribute(down_mma,   cudaFuncAttributePreferredSharedMemoryCarveout,
                         cudaSharedmemCarveoutMaxShared);

    cvt_gu_router_kernel<<<NCH_GU2/256, 256>>>(gate_w, up_w, hidden, router_w);
    build_kernel<<<1, 512>>>();
    gather_kernel<<<(NCH_AX + 255)/256, 256>>>(hidden);

    dim3 gridG(16, 32, E_NUM);
    gateup_mma<<<gridG, 256, GU_SMEM>>>(down_w);

    dim3 gridD(8, 32, E_NUM);
    down_mma<<<gridD, 256, DN_SMEM>>>();

    combine_kernel<<<T_TOK, 256>>>(out);
}

// round 14
// speedup vs baseline: 1.2257x; 1.0293x over previous
#include <cuda_runtime.h>
#include <cuda_fp16.h>
#include <math.h>
#include <cstdint>

// Problem constants
#define T_TOK   2048
#define H_DIM   1024
#define E_NUM   16
#define I_DIM   1024
#define NPAIR   (T_TOK*2)
#define NMT     48
#define NPAD    (NMT*128)
#define WELEM   (E_NUM*I_DIM*H_DIM)

// Tiled/swizzled storage (bytes)
__device__ __align__(16) unsigned char g_gate_t[16*16*32*4096];
__device__ __align__(16) unsigned char g_up_t  [16*16*32*4096];
__device__ __align__(16) unsigned char g_down_t[16*8*32*8192];
__device__ __align__(16) unsigned char g_ax    [NMT*32*8192];
__device__ __align__(16) unsigned char g_act2  [NMT*32*8192];
__device__ float  g_part[NPAD * H_DIM];
__device__ int    g_expert_of[NPAIR];
__device__ float  g_weight_of[NPAIR];
__device__ int    g_base [E_NUM];
__device__ int    g_count[E_NUM];
__device__ int    g_pair_token[NPAD];
__device__ float  g_pair_w   [NPAD];
__device__ int    g_slot_of  [NPAIR];

// ---------------------------------------------------------------------------
// helpers
// ---------------------------------------------------------------------------
__device__ __forceinline__ uint32_t smem_u32(const void* p) {
    uint32_t a;
    asm("{ .reg .u64 t; cvta.to.shared.u64 t, %1; cvt.u32.u64 %0, t; }" : "=r"(a) : "l"(p));
    return a;
}
__device__ __forceinline__ void ldsm_x4(uint32_t* r, uint32_t addr) {
    asm volatile("ldmatrix.sync.aligned.m8n8.x4.shared.b16 {%0,%1,%2,%3}, [%4];"
                 : "=r"(r[0]), "=r"(r[1]), "=r"(r[2]), "=r"(r[3]) : "r"(addr));
}
__device__ __forceinline__ void mma16816(float* c, const uint32_t* a, const uint32_t* b) {
    asm volatile("mma.sync.aligned.m16n8k16.row.col.f32.f16.f16.f32 "
                 "{%0,%1,%2,%3}, {%4,%5,%6,%7}, {%8,%9}, {%0,%1,%2,%3};"
                 : "+f"(c[0]), "+f"(c[1]), "+f"(c[2]), "+f"(c[3])
                 : "r"(a[0]), "r"(a[1]), "r"(a[2]), "r"(a[3]), "r"(b[0]), "r"(b[1]));
}
__device__ __forceinline__ uint32_t packh2(float x, float y) {
    __half2 h = __floats2half2_rn(x, y);
    return *(uint32_t*)&h;
}
__device__ __forceinline__ void bulk_g2s(uint32_t smem_dst, const void* gsrc,
                                         uint32_t bytes, uint32_t mbar) {
    asm volatile("cp.async.bulk.shared::cluster.global.mbarrier::complete_tx::bytes "
                 "[%0], [%1], %2, [%3];"
                 :: "r"(smem_dst), "l"(gsrc), "r"(bytes), "r"(mbar) : "memory");
}
#define FENCE_ASYNC_SHARED() \
    asm volatile("fence.proxy.async.shared::cta;" ::: "memory")
#define MBARRIER_INIT(mbar, count) \
    asm volatile("mbarrier.init.shared.b64 [%0], %1;" \
        :: "r"((uint32_t)(mbar)), "r"((uint32_t)(count)) : "memory")
#define MBARRIER_EXPECT_TX(mbar, tx) \
    asm volatile("mbarrier.arrive.expect_tx.shared.b64 _, [%0], %1;" \
        :: "r"((uint32_t)(mbar)), "r"((uint32_t)(tx)) : "memory")
#define MBARRIER_WAIT_PARITY(mbar_addr, phase_parity) do { \
    uint32_t _mbar = (uint32_t)(mbar_addr); \
    uint32_t _parity = (uint32_t)(phase_parity); \
    uint32_t _done; \
    asm volatile("{\n\t.reg .pred p;\n\t" \
        "mbarrier.try_wait.parity.acquire.cta.shared::cta.b64 p, [%1], %2;\n\t" \
        "selp.b32 %0, 1, 0, p;\n\t}" \
        : "=r"(_done) : "r"(_mbar), "r"(_parity) : "memory"); \
    if (!_done) { \
        asm volatile("{\n\t.reg .pred P1;\n\t" \
            "WAIT_LOOP_%=:\n\t" \
            "mbarrier.try_wait.parity.acquire.cta.shared::cta.b64 P1, [%0], %1, 0x989680;\n\t" \
            "@P1 bra.uni WAIT_DONE_%=;\n\t" \
            "bra.uni WAIT_LOOP_%=;\n\t" \
            "WAIT_DONE_%=:\n\t}" \
            :: "r"(_mbar), "r"(_parity) : "memory"); \
    } \
} while (0)

#define SW64K(r) (((r) & 6) << 3)
#define STAGES 4

// ---------------------------------------------------------------------------
// 0) gate/up cvt + retile + router
// ---------------------------------------------------------------------------
#define NCH_GU  (16*16*32*256)
#define NCH_GU2 (2*NCH_GU)

__global__ void cvt_gu_router_kernel(const float* __restrict__ gw,
                                     const float* __restrict__ uw,
                                     const float* __restrict__ x,
                                     const float* __restrict__ rw) {
    int tid = threadIdx.x;
    int g = blockIdx.x * 256 + tid;
    {
        int c = (g < NCH_GU) ? g : g - NCH_GU;
        const float* src = (g < NCH_GU) ? gw : uw;
        unsigned char* dstb = (g < NCH_GU) ? g_gate_t : g_up_t;
        int b = c >> 8, w = c & 255;
        int e = b >> 9, nt = (b >> 5) & 15, ks = b & 31;
        int rloc = w >> 2, cc = w & 3;
        int row = nt*64 + rloc;
        size_t srcoff = ((size_t)(e*1024 + row))*1024 + (ks*4 + cc)*8;
        uint32_t dstoff = (uint32_t)b*4096 + ((uint32_t)(w*16) ^ SW64K(rloc));
        float4 a = *(const float4*)(src + srcoff);
        float4 bb = *(const float4*)(src + srcoff + 4);
        uint4 o;
        o.x = packh2(a.x, a.y);  o.y = packh2(a.z, a.w);
        o.z = packh2(bb.x, bb.y); o.w = packh2(bb.z, bb.w);
        *(uint4*)(dstb + dstoff) = o;
    }

    if (blockIdx.x < T_TOK) {
        int t = blockIdx.x;
        int warp = tid >> 5, lane = tid & 31;
        __shared__ float logits[E_NUM];
        const float* xr = x + (size_t)t * H_DIM;
        const float* w0p = rw + (size_t)(2*warp)     * H_DIM;
        const float* w1p = rw + (size_t)(2*warp + 1) * H_DIM;
        float s0 = 0.f, s1 = 0.f;
        #pragma unroll 4
        for (int h = lane; h < H_DIM; h += 32) {
            float xv = xr[h];
            s0 += xv * w0p[h];
            s1 += xv * w1p[h];
        }
        #pragma unroll
        for (int o = 16; o; o >>= 1) {
            s0 += __shfl_xor_sync(0xffffffffu, s0, o);
            s1 += __shfl_xor_sync(0xffffffffu, s1, o);
        }
        if (lane == 0) { logits[2*warp] = s0; logits[2*warp + 1] = s1; }
        __syncthreads();
        if (tid == 0) {
            float sc[E_NUM];
            #pragma unroll
            for (int e = 0; e < E_NUM; e++) sc[e] = 1.f / (1.f + expf(-logits[e]));
            int i0 = 0;
            #pragma unroll
            for (int e = 1; e < E_NUM; e++) if (sc[e] > sc[i0]) i0 = e;
            int i1 = -1;
            #pragma unroll
            for (int e = 0; e < E_NUM; e++) {
                if (e == i0) continue;
                if (i1 < 0 || sc[e] > sc[i1]) i1 = e;
            }
            float w0 = sc[i0], w1 = sc[i1];
            float inv = 1.f / (w0 + w1 + 1e-20f);
            g_expert_of[2*t]   = i0;  g_weight_of[2*t]   = w0 * inv;
            g_expert_of[2*t+1] = i1;  g_weight_of[2*t+1] = w1 * inv;
        }
    }
}

// ---------------------------------------------------------------------------
// 2) Build expert-sorted padded pair lists
// ---------------------------------------------------------------------------
__global__ void build_kernel() {
    __shared__ unsigned char eid[NPAIR];
    __shared__ int cnt[E_NUM], pb[E_NUM];
    int tid = threadIdx.x;
    int w = tid >> 5, lane = tid & 31;
    for (int p = tid; p < NPAIR; p += blockDim.x)
        eid[p] = (unsigned char)g_expert_of[p];
    for (int s = tid; s < NPAD; s += blockDim.x) {
        g_pair_token[s] = 0;
        g_pair_w[s]     = 0.f;
    }
    __syncthreads();
    if (w < E_NUM) {
        int c = 0;
        for (int p0 = 0; p0 < NPAIR; p0 += 32)
            c += __popc(__ballot_sync(0xffffffffu, eid[p0 + lane] == w));
        if (lane == 0) cnt[w] = c;
    }
    __syncthreads();
    if (tid == 0) {
        int acc = 0;
        for (int e = 0; e < E_NUM; e++) {
            pb[e] = acc;
            acc += ((cnt[e] + 127) >> 7) << 7;
        }
    }
    __syncthreads();
    if (w < E_NUM) {
        int e = w, pos = pb[e];
        for (int p0 = 0; p0 < NPAIR; p0 += 32) {
            int p = p0 + lane;
            bool m = (eid[p] == e);
            unsigned mask = __ballot_sync(0xffffffffu, m);
            if (m) {
                int s = pos + __popc(mask & ((1u << lane) - 1u));
                g_pair_token[s] = p >> 1;
                g_pair_w[s]     = g_weight_of[p];
                g_slot_of[p]    = s;
            }
            pos += __popc(mask);
        }
    }
    if (tid < E_NUM) { g_base[tid] = pb[tid]; g_count[tid] = cnt[tid]; }
}

// ---------------------------------------------------------------------------
// 2b) Gather x into tiled/swizzled fp16 layout
// ---------------------------------------------------------------------------
#define NCH_AX (NMT*32*512)

__global__ void gather_kernel(const float* __restrict__ x) {
    int g = blockIdx.x * blockDim.x + threadIdx.x;
    if (g >= NCH_AX) return;
    int mt = g >> 14, rem = g & 16383;
    int ks = rem >> 9, w = rem & 511;
    int rloc = w >> 2, cc = w & 3;
    int slot = (mt << 7) + rloc;
    int tok = g_pair_token[slot];
    const float* src = x + (size_t)tok * H_DIM + ks*32 + cc*8;
    float4 a = *(const float4*)src;
    float4 b = *(const float4*)(src + 4);
    uint4 o;
    o.x = packh2(a.x, a.y); o.y = packh2(a.z, a.w);
    o.z = packh2(b.x, b.y); o.w = packh2(b.z, b.w);
    *(uint4*)(g_ax + ((size_t)(mt*32 + ks) << 13)
                   + (((uint32_t)(w*16)) ^ SW64K(rloc))) = o;
}

// ---------------------------------------------------------------------------
// 3) gateup: syncthreads-hardened 4-stage bulk pipeline + down-cvt preamble
//    Per iter: wait full -> compute -> __syncthreads -> tid0 fills it+3.
//    Fill at end of iter `it` targets buffer (it-1)&3, consumed at it-1 and
//    protected by this iter's barrier: provably race-free.
// ---------------------------------------------------------------------------
#define GU_TX  16384
#define GU_SMEM 66560

__global__ __launch_bounds__(256, 2)
void gateup_mma(const float* __restrict__ dw) {
    int tid = threadIdx.x, lane = tid & 31, wid = tid >> 5;

    // fused down-weight cvt
    {
        int flat = blockIdx.x + blockIdx.y * 16 + blockIdx.z * 512;
        int c = flat * 256 + tid;
        int b = c >> 9, w = c & 511;
        int e = b >> 8, nt = (b >> 5) & 7, ks = b & 31;
        int rloc = w >> 2, cc = w & 3;
        int row = nt*128 + rloc;
        size_t srcoff = ((size_t)(e*1024 + row))*1024 + (ks*4 + cc)*8;
        float4 a = *(const float4*)(dw + srcoff);
        float4 bb = *(const float4*)(dw + srcoff + 4);
        uint4 o;
        o.x = packh2(a.x, a.y);  o.y = packh2(a.z, a.w);
        o.z = packh2(bb.x, bb.y); o.w = packh2(bb.z, bb.w);
        *(uint4*)(g_down_t + (uint32_t)b*8192 + ((uint32_t)(w*16) ^ SW64K(rloc))) = o;
    }

    int e  = blockIdx.z;
    int m0 = blockIdx.y * 128;
    int bx = blockIdx.x;
    int n0 = bx * 64;
    int cnt = g_count[e];
    if (m0 >= cnt) return;
    int pb = g_base[e];

    extern __shared__ char dsm[];
    uint32_t sb = smem_u32(dsm);
    __shared__ float wrow_s[128];

    if (tid == 0) {
        #pragma unroll
        for (int s = 0; s < STAGES; s++) MBARRIER_INIT(sb + s*8, 1);
        FENCE_ASYNC_SHARED();
    }
    if (tid < 128) wrow_s[tid] = g_pair_w[pb + m0 + tid];
    __syncthreads();

    int mtg = (pb + m0) >> 7;
    const unsigned char* Asrc = g_ax     + (size_t)mtg * 32 * 8192;
    const unsigned char* Gsrc = g_gate_t + ((size_t)(e*16 + bx) * 32) * 4096;
    const unsigned char* Usrc = g_up_t   + ((size_t)(e*16 + bx) * 32) * 4096;

    int wm = wid & 3, wn = wid >> 2;
    int m_base = wm * 32, n_base = wn * 32;

    uint32_t relA[2];
    #pragma unroll
    for (int i = 0; i < 2; i++) {
        int r = m_base + i*16 + (lane & 15);
        relA[i] = (uint32_t)(r*64) + (((uint32_t)(lane >> 4) * 16) ^ SW64K(r));
    }
    uint32_t relB[2];
    #pragma unroll
    for (int jj = 0; jj < 2; jj++) {
        int r = n_base + jj*16 + (lane & 7) + (((lane >> 4) & 1) << 3);
        relB[jj] = (uint32_t)(r*64) + ((((uint32_t)(lane >> 3) & 1) * 16) ^ SW64K(r));
    }

    float cg[2][4][4] = {}, cu[2][4][4] = {};

    // prologue: fill stages 0..2 (after init+fence+sync above)
    if (tid == 0) {
        #pragma unroll
        for (int s = 0; s < STAGES-1; s++) {
            uint32_t fb = sb + s*8;
            MBARRIER_EXPECT_TX(fb, GU_TX);
            bulk_g2s(sb + 1024  + s*8192, Asrc + (size_t)s*8192, 8192, fb);
            bulk_g2s(sb + 33792 + s*4096, Gsrc + (size_t)s*4096, 4096, fb);
            bulk_g2s(sb + 50176 + s*4096, Usrc + (size_t)s*4096, 4096, fb);
        }
    }

    const int NIT = H_DIM / 32;
    for (int it = 0; it < NIT; it++) {
        int cs = it & 3;
        MBARRIER_WAIT_PARITY(sb + cs*8, (it >> 2) & 1);
        uint32_t bA = sb + 1024 + cs*8192;
        uint32_t bG = sb + 33792 + cs*4096;
        uint32_t bU = sb + 50176 + cs*4096;
        #pragma unroll
        for (int ks = 0; ks < 2; ks++) {
            uint32_t kk = (uint32_t)ks << 5;
            uint32_t a[2][4];
            #pragma unroll
            for (int i = 0; i < 2; i++) ldsm_x4(a[i], bA + (relA[i] ^ kk));
            uint32_t bg[2][4], bu[2][4];
            #pragma unroll
            for (int jj = 0; jj < 2; jj++) {
                ldsm_x4(bg[jj], bG + (relB[jj] ^ kk));
                ldsm_x4(bu[jj], bU + (relB[jj] ^ kk));
            }
            #pragma unroll
            for (int i = 0; i < 2; i++)
                #pragma unroll
                for (int jj = 0; jj < 2; jj++) {
                    mma16816(cg[i][2*jj+0], a[i], &bg[jj][0]);
                    mma16816(cg[i][2*jj+1], a[i], &bg[jj][2]);
                    mma16816(cu[i][2*jj+0], a[i], &bu[jj][0]);
                    mma16816(cu[i][2*jj+1], a[i], &bu[jj][2]);
                }
        }
        __syncthreads();   // everyone done consuming buffer cs (iter it)
        if (tid == 0 && it + STAGES-1 < NIT) {
            int j = it + STAGES-1, s = j & 3;   // buffer (it-1)&3, free since it-1
            uint32_t fb = sb + s*8;
            MBARRIER_EXPECT_TX(fb, GU_TX);
            bulk_g2s(sb + 1024  + s*8192, Asrc + (size_t)j*8192, 8192, fb);
            bulk_g2s(sb + 33792 + s*4096, Gsrc + (size_t)j*4096, 4096, fb);
            bulk_g2s(sb + 50176 + s*4096, Usrc + (size_t)j*4096, 4096, fb);
        }
    }

    // epilogue: write w*silu(g)*u into down's tiled layout (skip padded rows)
    int ks2 = (n0 >> 5) + wn;
    unsigned char* actb = g_act2 + ((size_t)(mtg*32 + ks2)) * 8192;
    uint32_t toff = (uint32_t)(lane & 3) * 4;
    #pragma unroll
    for (int i = 0; i < 2; i++) {
        #pragma unroll
        for (int h = 0; h < 2; h++) {
            int ml = m_base + i*16 + h*8 + (lane >> 2);
            int m  = m0 + ml;
            if (m >= cnt) continue;
            float w = wrow_s[ml];
            uint32_t rbase = (uint32_t)(ml*64);
            uint32_t kr = SW64K(ml);
            #pragma unroll
            for (int j = 0; j < 4; j++) {
                float g0 = cg[i][j][h*2+0], g1 = cg[i][j][h*2+1];
                float u0 = cu[i][j][h*2+0], u1 = cu[i][j][h*2+1];
                float a0 = w * (g0 / (1.f + __expf(-g0))) * u0;
                float a1 = w * (g1 / (1.f + __expf(-g1))) * u1;
                uint32_t off = rbase + (((uint32_t)(j*16)) ^ kr) + toff;
                *(uint32_t*)(actb + off) = packh2(a0, a1);
            }
        }
    }
}

// ---------------------------------------------------------------------------
// 4) down: syncthreads-hardened 4-stage bulk pipeline -> g_part
// ---------------------------------------------------------------------------
#define DN_TX  16384
#define DN_SMEM 66560

__global__ __launch_bounds__(256, 2)
void down_mma() {
    int e  = blockIdx.z;
    int m0 = blockIdx.y * 128;
    int bx = blockIdx.x;
    int n0 = bx * 128;
    int cnt = g_count[e];
    if (m0 >= cnt) return;
    int pb = g_base[e];

    extern __shared__ char dsm[];
    uint32_t sb = smem_u32(dsm);

    int tid = threadIdx.x, lane = tid & 31, wid = tid >> 5;
    if (tid == 0) {
        #pragma unroll
        for (int s = 0; s < STAGES; s++) MBARRIER_INIT(sb + s*8, 1);
        FENCE_ASYNC_SHARED();
    }
    __syncthreads();

    int mtg = (pb + m0) >> 7;
    const unsigned char* Asrc = g_act2   + (size_t)mtg * 32 * 8192;
    const unsigned char* Bsrc = g_down_t + ((size_t)(e*8 + bx) * 32) * 8192;

    int wm = wid & 3, wn = wid >> 2;
    int m_base = wm * 32, n_base = wn * 64;

    uint32_t relA[2];
    #pragma unroll
    for (int i = 0; i < 2; i++) {
        int r = m_base + i*16 + (lane & 15);
        relA[i] = (uint32_t)(r*64) + (((uint32_t)(lane >> 4) * 16) ^ SW64K(r));
    }
    uint32_t relB[4];
    #pragma unroll
    for (int jj = 0; jj < 4; jj++) {
        int r = n_base + jj*16 + (lane & 7) + (((lane >> 4) & 1) << 3);
        relB[jj] = (uint32_t)(r*64) + ((((uint32_t)(lane >> 3) & 1) * 16) ^ SW64K(r));
    }

    float cc[2][8][4] = {};

    if (tid == 0) {
        #pragma unroll
        for (int s = 0; s < STAGES-1; s++) {
            uint32_t fb = sb + s*8;
            MBARRIER_EXPECT_TX(fb, DN_TX);
            bulk_g2s(sb + 1024  + s*8192, Asrc + (size_t)s*8192, 8192, fb);
            bulk_g2s(sb + 33792 + s*8192, Bsrc + (size_t)s*8192, 8192, fb);
        }
    }

    const int NIT = I_DIM / 32;
    for (int it = 0; it < NIT; it++) {
        int cs = it & 3;
        MBARRIER_WAIT_PARITY(sb + cs*8, (it >> 2) & 1);
        uint32_t bA = sb + 1024 + cs*8192;
        uint32_t bB = sb + 33792 + cs*8192;
        #pragma unroll
        for (int ks = 0; ks < 2; ks++) {
            uint32_t kk = (uint32_t)ks << 5;
            uint32_t a[2][4];
            #pragma unroll
            for (int i = 0; i < 2; i++) ldsm_x4(a[i], bA + (relA[i] ^ kk));
            uint32_t b[4][4];
            #pragma unroll
            for (int jj = 0; jj < 4; jj++) ldsm_x4(b[jj], bB + (relB[jj] ^ kk));
            #pragma unroll
            for (int i = 0; i < 2; i++)
                #pragma unroll
                for (int jj = 0; jj < 4; jj++) {
                    mma16816(cc[i][2*jj+0], a[i], &b[jj][0]);
                    mma16816(cc[i][2*jj+1], a[i], &b[jj][2]);
                }
        }
        __syncthreads();
        if (tid == 0 && it + STAGES-1 < NIT) {
            int j = it + STAGES-1, s = j & 3;
            uint32_t fb = sb + s*8;
            MBARRIER_EXPECT_TX(fb, DN_TX);
            bulk_g2s(sb + 1024  + s*8192, Asrc + (size_t)j*8192, 8192, fb);
            bulk_g2s(sb + 33792 + s*8192, Bsrc + (size_t)j*8192, 8192, fb);
        }
    }

    #pragma unroll
    for (int i = 0; i < 2; i++) {
        #pragma unroll
        for (int h = 0; h < 2; h++) {
            int ml = m_base + i*16 + h*8 + (lane >> 2);
            int m  = m0 + ml;
            if (m >= cnt) continue;
            float* prow = g_part + (size_t)(pb + m0 + ml) * H_DIM + n0;
            #pragma unroll
            for (int j = 0; j < 8; j++) {
                int nl = n_base + j*8 + 2*(lane & 3);
                *(float2*)&prow[nl] = make_float2(cc[i][j][h*2+0], cc[i][j][h*2+1]);
            }
        }
    }
}

// ---------------------------------------------------------------------------
// 5) Combine
// ---------------------------------------------------------------------------
__global__ void combine_kernel(float* __restrict__ out) {
    int t = blockIdx.x;
    int s0 = g_slot_of[2*t], s1 = g_slot_of[2*t + 1];
    const float4* p0 = (const float4*)(g_part + (size_t)s0 * H_DIM);
    const float4* p1 = (const float4*)(g_part + (size_t)s1 * H_DIM);
    float4* o = (float4*)(out + (size_t)t * H_DIM);
    for (int i = threadIdx.x; i < H_DIM / 4; i += blockDim.x) {
        float4 a = p0[i], b = p1[i];
        o[i] = make_float4(a.x + b.x, a.y + b.y, a.z + b.z, a.w + b.w);
    }
}

// ---------------------------------------------------------------------------
extern "C" void kernel_launch(void* const* d_in, const int* in_sizes, int n_in,
                              void* d_out, int out_size) {
    const float* hidden   = (const float*)d_in[0];
    const float* router_w = (const float*)d_in[1];
    const float* gate_w   = (const float*)d_in[2];
    const float* up_w     = (const float*)d_in[3];
    const float* down_w   = (const float*)d_in[4];
    float* out = (float*)d_out;

    cudaFuncSetAttribute(gateup_mma, cudaFuncAttributeMaxDynamicSharedMemorySize, GU_SMEM);
    cudaFuncSetAttribute(down_mma,   cudaFuncAttributeMaxDynamicSharedMemorySize, DN_SMEM);
    cudaFuncSetAttribute(gateup_mma, cudaFuncAttributePreferredSharedMemoryCarveout,
                         cudaSharedmemCarveoutMaxShared);
    cudaFuncSetAttribute(down_mma,   cudaFuncAttributePreferredSharedMemoryCarveout,
                         cudaSharedmemCarveoutMaxShared);

    cvt_gu_router_kernel<<<NCH_GU2/256, 256>>>(gate_w, up_w, hidden, router_w);
    build_kernel<<<1, 512>>>();
    gather_kernel<<<(NCH_AX + 255)/256, 256>>>(hidden);

    dim3 gridG(16, 32, E_NUM);
    gateup_mma<<<gridG, 256, GU_SMEM>>>(down_w);

    dim3 gridD(8, 32, E_NUM);
    down_mma<<<gridD, 256, DN_SMEM>>>();

    combine_kernel<<<T_TOK, 256>>>(out);
}